// round 7
// baseline (speedup 1.0000x reference)
#include <cuda_runtime.h>
#include <cuda_fp16.h>
#include <math.h>

#define NMAX 100000
#define EMAX 800000
#define HCD  128     // H*C = 4*32
#define NH   4       // heads

// ---------------- scratch ----------------------------------------------------
__device__ float  g_Q [(size_t)NMAX * HCD];
__device__ __half g_KV[(size_t)NMAX * 2 * HCD];   // per node: 128 K halfs, 128 V halfs
__device__ float  g_Ha[(size_t)NMAX * HCD];
__device__ float  g_Hb[(size_t)NMAX * HCD];
__device__ int    g_src[EMAX];
__device__ int    g_dst[EMAX];
__device__ int    g_deg[NMAX + 1];
__device__ int    g_rowptr[NMAX + 1];
__device__ int    g_fill[NMAX];
__device__ int    g_csrc[EMAX];
__device__ float  g_cea[EMAX];

// ---------------- helpers -----------------------------------------------------
__device__ __forceinline__ unsigned tf32cvt(float f) {
    unsigned u;
    asm("cvt.rna.tf32.f32 %0, %1;" : "=r"(u) : "f"(f));
    return u;
}

__device__ __forceinline__ void mma_tf32(float* c, const unsigned* a, const unsigned* b) {
    asm volatile(
        "mma.sync.aligned.m16n8k8.row.col.f32.tf32.tf32.f32 "
        "{%0,%1,%2,%3}, {%4,%5,%6,%7}, {%8,%9}, {%0,%1,%2,%3};"
        : "+f"(c[0]), "+f"(c[1]), "+f"(c[2]), "+f"(c[3])
        : "r"(a[0]), "r"(a[1]), "r"(a[2]), "r"(a[3]), "r"(b[0]), "r"(b[1]));
}

__device__ __forceinline__ void storeAfrag(float* sA, int row, int k, float v) {
    int w = row >> 4, r = row & 15, s = k >> 3, kk = k & 7;
    int lane = ((r & 7) << 2) | (kk & 3);
    int ii   = (r >> 3) | ((kk >> 2) << 1);
    sA[(((w * 16 + s) * 32) + lane) * 4 + ii] = v;
}

// ---------------- edge_index normalization + degree histogram -------------------
__global__ void convert_ei_kernel(const int* __restrict__ p, int E,
                                  int* __restrict__ src, int* __restrict__ dst,
                                  int* __restrict__ deg) {
    __shared__ int s_is64;
    if (threadIdx.x == 0) {
        int is64 = 1;
        for (int i = 0; i < 64; i++)
            if (p[2 * i + 1] != 0) { is64 = 0; break; }
        s_is64 = is64;
    }
    __syncthreads();
    const int is64 = s_is64;
    int e = blockIdx.x * blockDim.x + threadIdx.x;
    if (e >= E) return;
    int s, d;
    if (is64) { s = p[2 * e]; d = p[2 * (E + e)]; }
    else      { s = p[e];     d = p[E + e]; }
    src[e] = s; dst[e] = d;
    atomicAdd(&deg[d], 1);
}

// ---------------- single-block exclusive scan over degrees ----------------------
__global__ void scan_kernel(const int* __restrict__ deg, int* __restrict__ rowptr, int n) {
    __shared__ int sm[1024];
    int tid = threadIdx.x;
    int chunk = (n + 1023) >> 10;
    int start = tid * chunk;
    int end = min(start + chunk, n);
    int sum = 0;
    for (int i = start; i < end; i++) sum += deg[i];
    sm[tid] = sum;
    __syncthreads();
    for (int d = 1; d < 1024; d <<= 1) {
        int v = (tid >= d) ? sm[tid - d] : 0;
        __syncthreads();
        sm[tid] += v;
        __syncthreads();
    }
    int off = sm[tid] - sum;   // exclusive
    for (int i = start; i < end; i++) { rowptr[i] = off; off += deg[i]; }
    if (tid == 1023) rowptr[n] = off;
}

// ---------------- fused scatter (CSR) + layer-0 projection ----------------------
// Blocks [0, EB): scatter edges into CSR. Blocks [EB, EB+NB): proj0.
__global__ void scatter_proj0_kernel(
    const int* __restrict__ src, const int* __restrict__ dst,
    const float* __restrict__ ea,
    const int* __restrict__ rowptr, int* __restrict__ fill,
    int* __restrict__ csrc, float* __restrict__ cea, int E, int EB,
    const float* __restrict__ x,
    const float* __restrict__ Wq, const float* __restrict__ bq,
    const float* __restrict__ Wk, const float* __restrict__ bk,
    const float* __restrict__ Wv, const float* __restrict__ bv,
    const float* __restrict__ Ws, const float* __restrict__ bs,
    float* __restrict__ Q, __half* __restrict__ KV,
    float* __restrict__ S, int n) {
    if (blockIdx.x < EB) {
        int e = blockIdx.x * blockDim.x + threadIdx.x;
        if (e >= E) return;
        int d = dst[e];
        int pos = rowptr[d] + atomicAdd(&fill[d], 1);
        csrc[pos] = src[e];
        cea[pos]  = ea[e];
    } else {
        int i = (blockIdx.x - EB) * blockDim.x + threadIdx.x;
        if (i >= n * HCD) return;
        int node = i >> 7;
        int c    = i & (HCD - 1);
        float x0 = __ldg(&x[node * 2 + 0]);
        float x1 = __ldg(&x[node * 2 + 1]);
        float qv = fmaf(x0, __ldg(&Wq[c]), fmaf(x1, __ldg(&Wq[HCD + c]), __ldg(&bq[c])));
        float kv = fmaf(x0, __ldg(&Wk[c]), fmaf(x1, __ldg(&Wk[HCD + c]), __ldg(&bk[c])));
        float vv = fmaf(x0, __ldg(&Wv[c]), fmaf(x1, __ldg(&Wv[HCD + c]), __ldg(&bv[c])));
        float sv = fmaf(x0, __ldg(&Ws[c]), fmaf(x1, __ldg(&Ws[HCD + c]), __ldg(&bs[c])));
        Q[i] = qv;
        S[i] = sv;
        KV[(size_t)node * 256 + c]       = __float2half_rn(kv);
        KV[(size_t)node * 256 + 128 + c] = __float2half_rn(vv);
    }
}

// ---------------- fused single-pass edge kernel (warp per dst node) --------------
// logit = (q.k[src] + eat*(q.We)) * scale ;  out = skip + (Σ ex v + (Σ ex eat) We)/Σ ex
__global__ __launch_bounds__(256)
void tconv_kernel(const int* __restrict__ rowptr, const int* __restrict__ csrc,
                  const float* __restrict__ cea,
                  const float* __restrict__ Q, const __half* __restrict__ KV,
                  const float* __restrict__ We,
                  float* __restrict__ H, int n) {
    int node = (blockIdx.x * blockDim.x + threadIdx.x) >> 5;
    if (node >= n) return;
    int lane = threadIdx.x & 31;
    int r0 = __ldg(&rowptr[node]);
    int r1 = __ldg(&rowptr[node + 1]);
    int c0 = lane * 4;

    float4 q = *(const float4*)(Q + (size_t)node * HCD + c0);
    float4 w = *(const float4*)(We + c0);

    // per-head q.We (uniform within each 8-lane head group after reduction)
    float qw = q.x * w.x + q.y * w.y + q.z * w.z + q.w * w.w;
    qw += __shfl_xor_sync(0xffffffffu, qw, 1);
    qw += __shfl_xor_sync(0xffffffffu, qw, 2);
    qw += __shfl_xor_sync(0xffffffffu, qw, 4);

    const float SC = 0.17677669529663687f;   // 1/sqrt(32)
    float den = 0.f, sev = 0.f;
    float4 acc = make_float4(0.f, 0.f, 0.f, 0.f);

    int e = r0;
    for (; e + 4 <= r1; e += 4) {
        int   s0 = __ldg(&csrc[e]),     s1 = __ldg(&csrc[e + 1]);
        int   s2 = __ldg(&csrc[e + 2]), s3 = __ldg(&csrc[e + 3]);
        float a0 = __ldg(&cea[e]),      a1 = __ldg(&cea[e + 1]);
        float a2 = __ldg(&cea[e + 2]),  a3 = __ldg(&cea[e + 3]);

        uint2 k0 = *(const uint2*)(KV + (size_t)s0 * 256 + c0);
        uint2 k1 = *(const uint2*)(KV + (size_t)s1 * 256 + c0);
        uint2 k2 = *(const uint2*)(KV + (size_t)s2 * 256 + c0);
        uint2 k3 = *(const uint2*)(KV + (size_t)s3 * 256 + c0);
        uint2 v0 = *(const uint2*)(KV + (size_t)s0 * 256 + 128 + c0);
        uint2 v1 = *(const uint2*)(KV + (size_t)s1 * 256 + 128 + c0);
        uint2 v2 = *(const uint2*)(KV + (size_t)s2 * 256 + 128 + c0);
        uint2 v3 = *(const uint2*)(KV + (size_t)s3 * 256 + 128 + c0);

        float2 kA, kB;
        kA = __half22float2(*(__half2*)&k0.x); kB = __half22float2(*(__half2*)&k0.y);
        float p0 = q.x * kA.x + q.y * kA.y + q.z * kB.x + q.w * kB.y;
        kA = __half22float2(*(__half2*)&k1.x); kB = __half22float2(*(__half2*)&k1.y);
        float p1 = q.x * kA.x + q.y * kA.y + q.z * kB.x + q.w * kB.y;
        kA = __half22float2(*(__half2*)&k2.x); kB = __half22float2(*(__half2*)&k2.y);
        float p2 = q.x * kA.x + q.y * kA.y + q.z * kB.x + q.w * kB.y;
        kA = __half22float2(*(__half2*)&k3.x); kB = __half22float2(*(__half2*)&k3.y);
        float p3 = q.x * kA.x + q.y * kA.y + q.z * kB.x + q.w * kB.y;

        p0 += __shfl_xor_sync(0xffffffffu, p0, 1);
        p1 += __shfl_xor_sync(0xffffffffu, p1, 1);
        p2 += __shfl_xor_sync(0xffffffffu, p2, 1);
        p3 += __shfl_xor_sync(0xffffffffu, p3, 1);
        p0 += __shfl_xor_sync(0xffffffffu, p0, 2);
        p1 += __shfl_xor_sync(0xffffffffu, p1, 2);
        p2 += __shfl_xor_sync(0xffffffffu, p2, 2);
        p3 += __shfl_xor_sync(0xffffffffu, p3, 2);
        p0 += __shfl_xor_sync(0xffffffffu, p0, 4);
        p1 += __shfl_xor_sync(0xffffffffu, p1, 4);
        p2 += __shfl_xor_sync(0xffffffffu, p2, 4);
        p3 += __shfl_xor_sync(0xffffffffu, p3, 4);

        float ex0 = expf((p0 + a0 * qw) * SC);
        float ex1 = expf((p1 + a1 * qw) * SC);
        float ex2 = expf((p2 + a2 * qw) * SC);
        float ex3 = expf((p3 + a3 * qw) * SC);

        den += (ex0 + ex1) + (ex2 + ex3);
        sev += (ex0 * a0 + ex1 * a1) + (ex2 * a2 + ex3 * a3);

        float2 vA, vB;
        vA = __half22float2(*(__half2*)&v0.x); vB = __half22float2(*(__half2*)&v0.y);
        acc.x = fmaf(vA.x, ex0, acc.x); acc.y = fmaf(vA.y, ex0, acc.y);
        acc.z = fmaf(vB.x, ex0, acc.z); acc.w = fmaf(vB.y, ex0, acc.w);
        vA = __half22float2(*(__half2*)&v1.x); vB = __half22float2(*(__half2*)&v1.y);
        acc.x = fmaf(vA.x, ex1, acc.x); acc.y = fmaf(vA.y, ex1, acc.y);
        acc.z = fmaf(vB.x, ex1, acc.z); acc.w = fmaf(vB.y, ex1, acc.w);
        vA = __half22float2(*(__half2*)&v2.x); vB = __half22float2(*(__half2*)&v2.y);
        acc.x = fmaf(vA.x, ex2, acc.x); acc.y = fmaf(vA.y, ex2, acc.y);
        acc.z = fmaf(vB.x, ex2, acc.z); acc.w = fmaf(vB.y, ex2, acc.w);
        vA = __half22float2(*(__half2*)&v3.x); vB = __half22float2(*(__half2*)&v3.y);
        acc.x = fmaf(vA.x, ex3, acc.x); acc.y = fmaf(vA.y, ex3, acc.y);
        acc.z = fmaf(vB.x, ex3, acc.z); acc.w = fmaf(vB.y, ex3, acc.w);
    }
    for (; e < r1; e++) {
        int   s0 = __ldg(&csrc[e]);
        float a0 = __ldg(&cea[e]);
        uint2 k0 = *(const uint2*)(KV + (size_t)s0 * 256 + c0);
        uint2 v0 = *(const uint2*)(KV + (size_t)s0 * 256 + 128 + c0);
        float2 kA = __half22float2(*(__half2*)&k0.x);
        float2 kB = __half22float2(*(__half2*)&k0.y);
        float p0 = q.x * kA.x + q.y * kA.y + q.z * kB.x + q.w * kB.y;
        p0 += __shfl_xor_sync(0xffffffffu, p0, 1);
        p0 += __shfl_xor_sync(0xffffffffu, p0, 2);
        p0 += __shfl_xor_sync(0xffffffffu, p0, 4);
        float ex0 = expf((p0 + a0 * qw) * SC);
        den += ex0;
        sev += ex0 * a0;
        float2 vA = __half22float2(*(__half2*)&v0.x);
        float2 vB = __half22float2(*(__half2*)&v0.y);
        acc.x = fmaf(vA.x, ex0, acc.x); acc.y = fmaf(vA.y, ex0, acc.y);
        acc.z = fmaf(vB.x, ex0, acc.z); acc.w = fmaf(vB.y, ex0, acc.w);
    }

    float inv = 1.f / (den + 1e-16f);
    float4 out = *(const float4*)(H + (size_t)node * HCD + c0);  // skip term
    out.x = fmaf(fmaf(sev, w.x, acc.x), inv, out.x);
    out.y = fmaf(fmaf(sev, w.y, acc.y), inv, out.y);
    out.z = fmaf(fmaf(sev, w.z, acc.z), inv, out.z);
    out.w = fmaf(fmaf(sev, w.w, acc.w), inv, out.w);
    *(float4*)(H + (size_t)node * HCD + c0) = out;
}

// ---------------- shared GEMM building blocks (3xTF32) ---------------------------
template<bool RIN>
__device__ __forceinline__ void fillA(float* sA, const float* __restrict__ X,
                                      int node0, int n, int tid) {
    for (int base = tid * 4; base < 64 * 128; base += 128 * 4) {
        int row  = base >> 7;
        int k0   = base & 127;
        int node = node0 + row;
        float4 v = make_float4(0.f, 0.f, 0.f, 0.f);
        if (node < n) v = *(const float4*)(X + (size_t)node * 128 + k0);
        if (RIN) {
            v.x = fmaxf(v.x, 0.f); v.y = fmaxf(v.y, 0.f);
            v.z = fmaxf(v.z, 0.f); v.w = fmaxf(v.w, 0.f);
        }
        storeAfrag(sA, row, k0 + 0, v.x);
        storeAfrag(sA, row, k0 + 1, v.y);
        storeAfrag(sA, row, k0 + 2, v.z);
        storeAfrag(sA, row, k0 + 3, v.w);
    }
}

template<int NC>
__device__ __forceinline__ void fillB(float* sB, const float* __restrict__ W, int tid) {
    constexpr int JT = NC / 8;
    for (int base = tid * 4; base < 128 * NC; base += 128 * 4) {
        int k  = base / NC;
        int n0 = base % NC;
        float4 v = __ldg((const float4*)(W + (size_t)k * NC + n0));
        float vv[4] = {v.x, v.y, v.z, v.w};
        int s = k >> 3, kk = k & 7, ii = kk >> 2;
#pragma unroll
        for (int i = 0; i < 4; i++) {
            int nn = n0 + i, j = nn >> 3;
            int lane = ((nn & 7) << 2) | (kk & 3);
            sB[(((s * JT + j) * 32) + lane) * 2 + ii] = vv[i];
        }
    }
}

template<int JT>
__device__ __forceinline__ void computeTile(const float* sA, const float* sB,
                                            float acc[][4], int wid, int lane) {
#pragma unroll
    for (int s = 0; s < 16; s++) {
        float4 af = *(const float4*)&sA[(((wid * 16 + s) * 32) + lane) * 4];
        float afv[4] = {af.x, af.y, af.z, af.w};
        unsigned ahi[4], alo[4];
#pragma unroll
        for (int i = 0; i < 4; i++) {
            ahi[i] = tf32cvt(afv[i]);
            alo[i] = tf32cvt(afv[i] - __uint_as_float(ahi[i]));
        }
#pragma unroll
        for (int j = 0; j < JT; j++) {
            float2 bf = *(const float2*)&sB[(((s * JT + j) * 32) + lane) * 2];
            unsigned bhi[2], blo[2];
            bhi[0] = tf32cvt(bf.x); blo[0] = tf32cvt(bf.x - __uint_as_float(bhi[0]));
            bhi[1] = tf32cvt(bf.y); blo[1] = tf32cvt(bf.y - __uint_as_float(bhi[1]));
            mma_tf32(acc[j], ahi, bhi);
            mma_tf32(acc[j], alo, bhi);
            mma_tf32(acc[j], ahi, blo);
        }
    }
}

// ---------------- fused 4-projection GEMM (layer 1) ------------------------------
__global__ __launch_bounds__(128)
void gemm4_kernel(const float* __restrict__ X,
                  const float* __restrict__ W0, const float* __restrict__ b0, float* __restrict__ Q,
                  const float* __restrict__ W1, const float* __restrict__ b1,
                  const float* __restrict__ W2, const float* __restrict__ b2, __half* __restrict__ KV,
                  const float* __restrict__ W3, const float* __restrict__ b3, float* __restrict__ S,
                  int n) {
    extern __shared__ float smem[];
    float* sA = smem;                  // 8192 floats
    float* sB = smem + 8192;           // 16384 floats (JT=16)
    const int tid = threadIdx.x;
    const int wid = tid >> 5, lane = tid & 31;
    const int node0 = blockIdx.x * 64;

    fillA<true>(sA, X, node0, n, tid);

    const float* Wm[4] = {W0, W1, W2, W3};
    const float* bm[4] = {b0, b1, b2, b3};

    for (int m = 0; m < 4; m++) {
        __syncthreads();
        fillB<128>(sB, Wm[m], tid);
        __syncthreads();

        float acc[16][4];
#pragma unroll
        for (int j = 0; j < 16; j++) {
            float bb0 = __ldg(&bm[m][j * 8 + (lane & 3) * 2]);
            float bb1 = __ldg(&bm[m][j * 8 + (lane & 3) * 2 + 1]);
            acc[j][0] = bb0; acc[j][1] = bb1; acc[j][2] = bb0; acc[j][3] = bb1;
        }
        computeTile<16>(sA, sB, acc, wid, lane);

        int row0 = node0 + wid * 16 + (lane >> 2);
        int row1 = row0 + 8;
        if (m == 0 || m == 3) {
            float* Y = (m == 0) ? Q : S;
#pragma unroll
            for (int j = 0; j < 16; j++) {
                int col = j * 8 + (lane & 3) * 2;
                if (row0 < n) *(float2*)(Y + (size_t)row0 * 128 + col) = make_float2(acc[j][0], acc[j][1]);
                if (row1 < n) *(float2*)(Y + (size_t)row1 * 128 + col) = make_float2(acc[j][2], acc[j][3]);
            }
        } else {
            int off = (m == 1) ? 0 : 128;
#pragma unroll
            for (int j = 0; j < 16; j++) {
                int col = j * 8 + (lane & 3) * 2;
                __half2 h0 = __floats2half2_rn(acc[j][0], acc[j][1]);
                __half2 h1 = __floats2half2_rn(acc[j][2], acc[j][3]);
                if (row0 < n) *(__half2*)(KV + (size_t)row0 * 256 + off + col) = h0;
                if (row1 < n) *(__half2*)(KV + (size_t)row1 * 256 + off + col) = h1;
            }
        }
    }
}

// ---------------- fused classifier ------------------------------------------------
__global__ __launch_bounds__(128)
void classifier_kernel(const float* __restrict__ X,
                       const float* __restrict__ Wc1, const float* __restrict__ bc1,
                       const float* __restrict__ Wc2, const float* __restrict__ bc2,
                       const float* __restrict__ Wc3, const float* __restrict__ bc3,
                       float* __restrict__ out, int n) {
    extern __shared__ float smem[];
    float* sA = smem;
    float* sB = smem + 8192;
    const int tid = threadIdx.x;
    const int wid = tid >> 5, lane = tid & 31;
    const int node0 = blockIdx.x * 64;

    fillA<true>(sA, X, node0, n, tid);
    fillB<128>(sB, Wc1, tid);
    __syncthreads();

    float acc[16][4];
#pragma unroll
    for (int j = 0; j < 16; j++) {
        float bb0 = __ldg(&bc1[j * 8 + (lane & 3) * 2]);
        float bb1 = __ldg(&bc1[j * 8 + (lane & 3) * 2 + 1]);
        acc[j][0] = bb0; acc[j][1] = bb1; acc[j][2] = bb0; acc[j][3] = bb1;
    }
    computeTile<16>(sA, sB, acc, wid, lane);

    {
        int lr0 = wid * 16 + (lane >> 2);
        int lr1 = lr0 + 8;
#pragma unroll
        for (int j = 0; j < 16; j++) {
            int col = j * 8 + (lane & 3) * 2;
            storeAfrag(sA, lr0, col,     fmaxf(acc[j][0], 0.f));
            storeAfrag(sA, lr0, col + 1, fmaxf(acc[j][1], 0.f));
            storeAfrag(sA, lr1, col,     fmaxf(acc[j][2], 0.f));
            storeAfrag(sA, lr1, col + 1, fmaxf(acc[j][3], 0.f));
        }
    }
    __syncthreads();
    fillB<64>(sB, Wc2, tid);
    __syncthreads();

    float acc2[8][4];
#pragma unroll
    for (int j = 0; j < 8; j++) {
        float bb0 = __ldg(&bc2[j * 8 + (lane & 3) * 2]);
        float bb1 = __ldg(&bc2[j * 8 + (lane & 3) * 2 + 1]);
        acc2[j][0] = bb0; acc2[j][1] = bb1; acc2[j][2] = bb0; acc2[j][3] = bb1;
    }
    computeTile<8>(sA, sB, acc2, wid, lane);

    float p0 = 0.f, p1 = 0.f;
#pragma unroll
    for (int j = 0; j < 8; j++) {
        int c = j * 8 + (lane & 3) * 2;
        float w0 = __ldg(&Wc3[c]), w1 = __ldg(&Wc3[c + 1]);
        p0 += fmaxf(acc2[j][0], 0.f) * w0 + fmaxf(acc2[j][1], 0.f) * w1;
        p1 += fmaxf(acc2[j][2], 0.f) * w0 + fmaxf(acc2[j][3], 0.f) * w1;
    }
    p0 += __shfl_xor_sync(0xffffffffu, p0, 1);
    p0 += __shfl_xor_sync(0xffffffffu, p0, 2);
    p1 += __shfl_xor_sync(0xffffffffu, p1, 1);
    p1 += __shfl_xor_sync(0xffffffffu, p1, 2);

    if ((lane & 3) == 0) {
        float bv = __ldg(&bc3[0]);
        int row0 = node0 + wid * 16 + (lane >> 2);
        int row1 = row0 + 8;
        if (row0 < n) out[row0] = p0 + bv;
        if (row1 < n) out[row1] = p1 + bv;
    }
}

// ---------------- launch -----------------------------------------------------------
extern "C" void kernel_launch(void* const* d_in, const int* in_sizes, int n_in,
                              void* d_out, int out_size) {
    const float* x   = (const float*)d_in[0];
    const int*   eiw = (const int*)d_in[1];
    const float* ea  = (const float*)d_in[2];
    const float *Wq0 = (const float*)d_in[3],  *bq0 = (const float*)d_in[4];
    const float *Wk0 = (const float*)d_in[5],  *bk0 = (const float*)d_in[6];
    const float *Wv0 = (const float*)d_in[7],  *bv0 = (const float*)d_in[8];
    const float *We0 = (const float*)d_in[9];
    const float *Ws0 = (const float*)d_in[10], *bs0 = (const float*)d_in[11];
    const float *Wq1 = (const float*)d_in[12], *bq1 = (const float*)d_in[13];
    const float *Wk1 = (const float*)d_in[14], *bk1 = (const float*)d_in[15];
    const float *Wv1 = (const float*)d_in[16], *bv1 = (const float*)d_in[17];
    const float *We1 = (const float*)d_in[18];
    const float *Ws1 = (const float*)d_in[19], *bs1 = (const float*)d_in[20];
    const float *Wc1 = (const float*)d_in[21], *bc1 = (const float*)d_in[22];
    const float *Wc2 = (const float*)d_in[23], *bc2 = (const float*)d_in[24];
    const float *Wc3 = (const float*)d_in[25], *bc3 = (const float*)d_in[26];

    const int n = in_sizes[0] / 2;
    const int E = in_sizes[2];

    float *Q, *Ha, *Hb, *cea;
    __half* KV;
    int *src, *dst, *deg, *rowptr, *fill, *csrc;
    cudaGetSymbolAddress((void**)&Q,      g_Q);
    cudaGetSymbolAddress((void**)&KV,     g_KV);
    cudaGetSymbolAddress((void**)&Ha,     g_Ha);
    cudaGetSymbolAddress((void**)&Hb,     g_Hb);
    cudaGetSymbolAddress((void**)&src,    g_src);
    cudaGetSymbolAddress((void**)&dst,    g_dst);
    cudaGetSymbolAddress((void**)&deg,    g_deg);
    cudaGetSymbolAddress((void**)&rowptr, g_rowptr);
    cudaGetSymbolAddress((void**)&fill,   g_fill);
    cudaGetSymbolAddress((void**)&csrc,   g_csrc);
    cudaGetSymbolAddress((void**)&cea,    g_cea);

    const int TB = 256;
    const int EB = (E + TB - 1) / TB;              // edge blocks
    const int NB = (n * HCD + TB - 1) / TB;        // proj0 blocks
    dim3 nodeWarpGrid((n * 32 + TB - 1) / TB);
    dim3 tileGrid((n + 63) / 64);

    const int SMEM = (8192 + 16384) * 4;   // 98304 B
    cudaFuncSetAttribute(gemm4_kernel,      cudaFuncAttributeMaxDynamicSharedMemorySize, SMEM);
    cudaFuncSetAttribute(classifier_kernel, cudaFuncAttributeMaxDynamicSharedMemorySize, SMEM);

    cudaMemsetAsync(deg,  0, (n + 1) * sizeof(int));
    cudaMemsetAsync(fill, 0, n * sizeof(int));
    convert_ei_kernel<<<EB, TB>>>(eiw, E, src, dst, deg);                        // k1
    scan_kernel<<<1, 1024>>>(deg, rowptr, n);                                     // k2
    scatter_proj0_kernel<<<EB + NB, TB>>>(src, dst, ea, rowptr, fill,             // k3
                                          csrc, cea, E, EB,
                                          x, Wq0, bq0, Wk0, bk0, Wv0, bv0,
                                          Ws0, bs0, Q, KV, Ha, n);
    tconv_kernel<<<nodeWarpGrid, TB>>>(rowptr, csrc, cea, Q, KV, We0, Ha, n);    // k4 <- profiled
    gemm4_kernel<<<tileGrid, 128, SMEM>>>(Ha,                                     // k5
                                          Wq1, bq1, Q,
                                          Wk1, bk1,
                                          Wv1, bv1, KV,
                                          Ws1, bs1, Hb, n);
    tconv_kernel<<<nodeWarpGrid, TB>>>(rowptr, csrc, cea, Q, KV, We1, Hb, n);    // k6
    classifier_kernel<<<tileGrid, 128, SMEM>>>(Hb, Wc1, bc1, Wc2, bc2, Wc3, bc3,  // k7
                                               (float*)d_out, n);
}

// round 10
// speedup vs baseline: 2.0081x; 2.0081x over previous
#include <cuda_runtime.h>
#include <cuda_fp16.h>
#include <cstdint>
#include <math.h>

#define NMAX 100000
#define EMAX 800000
#define HCD  128     // H*C = 4*32
#define NH   4       // heads

// ---------------- scratch ----------------------------------------------------
__device__ float  g_Q [(size_t)NMAX * HCD];       // Q
__device__ __half g_KV[(size_t)NMAX * 2 * HCD];   // per node: 128 K halfs, 128 V halfs
__device__ float  g_Ha[(size_t)NMAX * HCD];       // layer0 out
__device__ float  g_Hb[(size_t)NMAX * HCD];       // layer1 out
__device__ int    g_src[EMAX];
__device__ int    g_dst[EMAX];
__device__ int    g_deg[NMAX + 1];
__device__ int    g_rowptr[NMAX + 1];
__device__ int    g_fill[NMAX];
__device__ int    g_csrc[EMAX];
__device__ float  g_cea[EMAX];

// ---------------- fp16 HMMA helpers ------------------------------------------
// smem word offsets (uint32 units)
#define A_HI_W 0
#define A_LO_W 4096
#define B_HI_W 8192
// B_LO_W = 8192 + 8*JT*64 (JT = NC/8)

__device__ __forceinline__ void mma_f16(float* c, const uint32_t* a, const uint32_t* b) {
    asm volatile(
        "mma.sync.aligned.m16n8k16.row.col.f32.f16.f16.f32 "
        "{%0,%1,%2,%3}, {%4,%5,%6,%7}, {%8,%9}, {%0,%1,%2,%3};"
        : "+f"(c[0]), "+f"(c[1]), "+f"(c[2]), "+f"(c[3])
        : "r"(a[0]), "r"(a[1]), "r"(a[2]), "r"(a[3]), "r"(b[0]), "r"(b[1]));
}

__device__ __forceinline__ uint32_t packh2(__half a, __half b) {
    __half2 h = __halves2half2(a, b);
    return *(uint32_t*)&h;
}

// ---- fill A: 64 rows x 128 k, fp16 hi/lo split, m16n8k16 fragment order --------
template<bool RIN>
__device__ __forceinline__ void fillA(uint32_t* smw, const float* __restrict__ X,
                                      int node0, int n, int tid) {
#pragma unroll
    for (int it = 0; it < 8; it++) {
        int cid = it * 128 + tid;          // 0..1023
        int row = cid >> 4;                // 0..63
        int k0  = (cid & 15) << 3;         // 0..120 step 8
        int node = node0 + row;
        float4 a = make_float4(0.f, 0.f, 0.f, 0.f), b = a;
        if (node < n) {
            const float4* xp = (const float4*)(X + (size_t)node * 128 + k0);
            a = xp[0]; b = xp[1];
        }
        if (RIN) {
            a.x = fmaxf(a.x, 0.f); a.y = fmaxf(a.y, 0.f);
            a.z = fmaxf(a.z, 0.f); a.w = fmaxf(a.w, 0.f);
            b.x = fmaxf(b.x, 0.f); b.y = fmaxf(b.y, 0.f);
            b.z = fmaxf(b.z, 0.f); b.w = fmaxf(b.w, 0.f);
        }
        float v[8] = {a.x, a.y, a.z, a.w, b.x, b.y, b.z, b.w};
        __half hh[8], hl[8];
#pragma unroll
        for (int j = 0; j < 8; j++) {
            hh[j] = __float2half_rn(v[j]);
            hl[j] = __float2half_rn(v[j] - __half2float(hh[j]));
        }
        int w = row >> 4, r = row & 15;
        int s = k0 >> 4;                   // k-step (16 wide)
        int kk8 = (k0 >> 3) & 1;           // which 8-half of the step
        int reg = (r >> 3) + 2 * kk8;
        int lane0 = (r & 7) * 4;
        int base = ((w * 8 + s) * 32 + lane0) * 4 + reg;
#pragma unroll
        for (int p = 0; p < 4; p++) {
            smw[A_HI_W + base + p * 4] = packh2(hh[2 * p], hh[2 * p + 1]);
            smw[A_LO_W + base + p * 4] = packh2(hl[2 * p], hl[2 * p + 1]);
        }
    }
}

// ---- fill B: W[128,NC] -> col-major fragments, hi/lo split ----------------------
template<int NC>
__device__ __forceinline__ void fillB(uint32_t* smw, const float* __restrict__ W, int tid) {
    constexpr int JT = NC / 8;
    constexpr int BLO = B_HI_W + 8 * JT * 64;
#pragma unroll
    for (int it = 0; it < NC / 8; it++) {
        int cid = it * 128 + tid;          // 0..16*NC-1
        int nr = cid & (NC - 1);
        int kc = cid / NC;                 // 0..15
        int k0 = kc << 3;
        float v[8];
#pragma unroll
        for (int j = 0; j < 8; j++) v[j] = __ldg(&W[(size_t)(k0 + j) * NC + nr]);
        __half hh[8], hl[8];
#pragma unroll
        for (int j = 0; j < 8; j++) {
            hh[j] = __float2half_rn(v[j]);
            hl[j] = __float2half_rn(v[j] - __half2float(hh[j]));
        }
        int j = nr >> 3, nn = nr & 7;
        int s = k0 >> 4;
        int reg = (k0 >> 3) & 1;
        int lane0 = nn * 4;
        int base = ((s * JT + j) * 32 + lane0) * 2 + reg;
#pragma unroll
        for (int p = 0; p < 4; p++) {
            smw[B_HI_W + base + p * 2] = packh2(hh[2 * p], hh[2 * p + 1]);
            smw[BLO    + base + p * 2] = packh2(hl[2 * p], hl[2 * p + 1]);
        }
    }
}

// ---- 3-term split MMA compute: acc += A(hi+lo) x B(hi) + A(hi) x B(lo) ---------
template<int JT>
__device__ __forceinline__ void computeTile(const uint32_t* smw, float acc[][4],
                                            int wid, int lane) {
    constexpr int BLO = B_HI_W + 8 * JT * 64;
#pragma unroll
    for (int s = 0; s < 8; s++) {
        uint4 ah4 = *(const uint4*)&smw[A_HI_W + ((wid * 8 + s) * 32 + lane) * 4];
        uint4 al4 = *(const uint4*)&smw[A_LO_W + ((wid * 8 + s) * 32 + lane) * 4];
        uint32_t ah[4] = {ah4.x, ah4.y, ah4.z, ah4.w};
        uint32_t al[4] = {al4.x, al4.y, al4.z, al4.w};
#pragma unroll
        for (int j = 0; j < JT; j++) {
            uint2 bh2 = *(const uint2*)&smw[B_HI_W + ((s * JT + j) * 32 + lane) * 2];
            uint2 bl2 = *(const uint2*)&smw[BLO    + ((s * JT + j) * 32 + lane) * 2];
            uint32_t bh[2] = {bh2.x, bh2.y};
            uint32_t bl[2] = {bl2.x, bl2.y};
            mma_f16(acc[j], ah, bh);
            mma_f16(acc[j], al, bh);
            mma_f16(acc[j], ah, bl);
        }
    }
}

// ---- store a value pair back into A fragments (for fused classifier) -----------
__device__ __forceinline__ void storeZfrag(uint32_t* smw, int lrow, int col,
                                           float v0, float v1) {
    int w = lrow >> 4, r = lrow & 15;
    int s = col >> 4, kk = col & 15;
    int reg = (r >> 3) + 2 * (kk >> 3);
    int lane = (r & 7) * 4 + ((kk & 7) >> 1);
    int idx = ((w * 8 + s) * 32 + lane) * 4 + reg;
    __half h0 = __float2half_rn(v0), h1 = __float2half_rn(v1);
    smw[A_HI_W + idx] = packh2(h0, h1);
    __half l0 = __float2half_rn(v0 - __half2float(h0));
    __half l1 = __float2half_rn(v1 - __half2float(h1));
    smw[A_LO_W + idx] = packh2(l0, l1);
}

// ---------------- fused 4-projection GEMM (layer 1), fp16 HMMA -------------------
__global__ __launch_bounds__(128)
void gemm4_hmma(const float* __restrict__ X,
                const float* __restrict__ W0, const float* __restrict__ b0, float* __restrict__ Q,
                const float* __restrict__ W1, const float* __restrict__ b1,
                const float* __restrict__ W2, const float* __restrict__ b2, __half* __restrict__ KV,
                const float* __restrict__ W3, const float* __restrict__ b3, float* __restrict__ S,
                int n) {
    extern __shared__ uint32_t smw[];
    const int tid = threadIdx.x, wid = tid >> 5, lane = tid & 31;
    const int node0 = blockIdx.x * 64;

    fillA<true>(smw, X, node0, n, tid);

    const float* Wm[4] = {W0, W1, W2, W3};
    const float* bm[4] = {b0, b1, b2, b3};

    int row0 = node0 + wid * 16 + (lane >> 2);
    int row1 = row0 + 8;

    for (int m = 0; m < 4; m++) {
        __syncthreads();               // prior compute done with sB
        fillB<128>(smw, Wm[m], tid);
        __syncthreads();

        float acc[16][4];
#pragma unroll
        for (int j = 0; j < 16; j++) {
            float bb0 = __ldg(&bm[m][j * 8 + (lane & 3) * 2]);
            float bb1 = __ldg(&bm[m][j * 8 + (lane & 3) * 2 + 1]);
            acc[j][0] = bb0; acc[j][1] = bb1; acc[j][2] = bb0; acc[j][3] = bb1;
        }
        computeTile<16>(smw, acc, wid, lane);

        if (m == 0 || m == 3) {
            float* Y = (m == 0) ? Q : S;
#pragma unroll
            for (int j = 0; j < 16; j++) {
                int col = j * 8 + (lane & 3) * 2;
                if (row0 < n) *(float2*)(Y + (size_t)row0 * 128 + col) = make_float2(acc[j][0], acc[j][1]);
                if (row1 < n) *(float2*)(Y + (size_t)row1 * 128 + col) = make_float2(acc[j][2], acc[j][3]);
            }
        } else {
            int off = (m == 1) ? 0 : 128;
#pragma unroll
            for (int j = 0; j < 16; j++) {
                int col = j * 8 + (lane & 3) * 2;
                if (row0 < n) *(__half2*)(KV + (size_t)row0 * 256 + off + col) = __floats2half2_rn(acc[j][0], acc[j][1]);
                if (row1 < n) *(__half2*)(KV + (size_t)row1 * 256 + off + col) = __floats2half2_rn(acc[j][2], acc[j][3]);
            }
        }
    }
}

// ---------------- fused classifier: relu(Hb)@Wc1 ->relu-> @Wc2 ->relu-> @Wc3 -----
__global__ __launch_bounds__(128)
void classifier_hmma(const float* __restrict__ X,
                     const float* __restrict__ Wc1, const float* __restrict__ bc1,
                     const float* __restrict__ Wc2, const float* __restrict__ bc2,
                     const float* __restrict__ Wc3, const float* __restrict__ bc3,
                     float* __restrict__ out, int n) {
    extern __shared__ uint32_t smw[];
    const int tid = threadIdx.x, wid = tid >> 5, lane = tid & 31;
    const int node0 = blockIdx.x * 64;

    fillA<true>(smw, X, node0, n, tid);
    fillB<128>(smw, Wc1, tid);
    __syncthreads();

    // stage 1: Z1 = relu(X @ Wc1 + bc1), 128 cols
    float acc[16][4];
#pragma unroll
    for (int j = 0; j < 16; j++) {
        float bb0 = __ldg(&bc1[j * 8 + (lane & 3) * 2]);
        float bb1 = __ldg(&bc1[j * 8 + (lane & 3) * 2 + 1]);
        acc[j][0] = bb0; acc[j][1] = bb1; acc[j][2] = bb0; acc[j][3] = bb1;
    }
    computeTile<16>(smw, acc, wid, lane);

    {
        int lr0 = wid * 16 + (lane >> 2);
        int lr1 = lr0 + 8;
#pragma unroll
        for (int j = 0; j < 16; j++) {
            int col = j * 8 + (lane & 3) * 2;
            storeZfrag(smw, lr0, col, fmaxf(acc[j][0], 0.f), fmaxf(acc[j][1], 0.f));
            storeZfrag(smw, lr1, col, fmaxf(acc[j][2], 0.f), fmaxf(acc[j][3], 0.f));
        }
    }
    __syncthreads();
    fillB<64>(smw, Wc2, tid);
    __syncthreads();

    // stage 2: Z2 = relu(Z1 @ Wc2 + bc2), 64 cols
    float acc2[8][4];
#pragma unroll
    for (int j = 0; j < 8; j++) {
        float bb0 = __ldg(&bc2[j * 8 + (lane & 3) * 2]);
        float bb1 = __ldg(&bc2[j * 8 + (lane & 3) * 2 + 1]);
        acc2[j][0] = bb0; acc2[j][1] = bb1; acc2[j][2] = bb0; acc2[j][3] = bb1;
    }
    computeTile<8>(smw, acc2, wid, lane);

    // stage 3: out = relu(Z2) @ Wc3 + bc3
    float p0 = 0.f, p1 = 0.f;
#pragma unroll
    for (int j = 0; j < 8; j++) {
        int c = j * 8 + (lane & 3) * 2;
        float w0 = __ldg(&Wc3[c]), w1 = __ldg(&Wc3[c + 1]);
        p0 += fmaxf(acc2[j][0], 0.f) * w0 + fmaxf(acc2[j][1], 0.f) * w1;
        p1 += fmaxf(acc2[j][2], 0.f) * w0 + fmaxf(acc2[j][3], 0.f) * w1;
    }
    p0 += __shfl_xor_sync(0xffffffffu, p0, 1);
    p0 += __shfl_xor_sync(0xffffffffu, p0, 2);
    p1 += __shfl_xor_sync(0xffffffffu, p1, 1);
    p1 += __shfl_xor_sync(0xffffffffu, p1, 2);

    if ((lane & 3) == 0) {
        float bv = __ldg(&bc3[0]);
        int row0 = node0 + wid * 16 + (lane >> 2);
        int row1 = row0 + 8;
        if (row0 < n) out[row0] = p0 + bv;
        if (row1 < n) out[row1] = p1 + bv;
    }
}

// ---------------- edge_index normalization + degree histogram -------------------
__global__ void convert_ei_kernel(const int* __restrict__ p, int E,
                                  int* __restrict__ src, int* __restrict__ dst,
                                  int* __restrict__ deg) {
    __shared__ int s_is64;
    if (threadIdx.x == 0) {
        int is64 = 1;
        for (int i = 0; i < 64; i++)
            if (p[2 * i + 1] != 0) { is64 = 0; break; }
        s_is64 = is64;
    }
    __syncthreads();
    const int is64 = s_is64;
    int e = blockIdx.x * blockDim.x + threadIdx.x;
    if (e >= E) return;
    int s, d;
    if (is64) { s = p[2 * e]; d = p[2 * (E + e)]; }
    else      { s = p[e];     d = p[E + e]; }
    src[e] = s; dst[e] = d;
    atomicAdd(&deg[d], 1);
}

// ---------------- single-block exclusive scan over degrees ----------------------
__global__ void scan_kernel(const int* __restrict__ deg, int* __restrict__ rowptr, int n) {
    __shared__ int sm[1024];
    int tid = threadIdx.x;
    int chunk = (n + 1023) >> 10;
    int start = tid * chunk;
    int end = min(start + chunk, n);
    int sum = 0;
    for (int i = start; i < end; i++) sum += deg[i];
    sm[tid] = sum;
    __syncthreads();
    for (int d = 1; d < 1024; d <<= 1) {
        int v = (tid >= d) ? sm[tid - d] : 0;
        __syncthreads();
        sm[tid] += v;
        __syncthreads();
    }
    int off = sm[tid] - sum;   // exclusive
    for (int i = start; i < end; i++) { rowptr[i] = off; off += deg[i]; }
    if (tid == 1023) rowptr[n] = off;
}

// ---------------- fused scatter (CSR) + layer-0 projection ----------------------
__global__ void scatter_proj0_kernel(
    const int* __restrict__ src, const int* __restrict__ dst,
    const float* __restrict__ ea,
    const int* __restrict__ rowptr, int* __restrict__ fill,
    int* __restrict__ csrc, float* __restrict__ cea, int E, int EB,
    const float* __restrict__ x,
    const float* __restrict__ Wq, const float* __restrict__ bq,
    const float* __restrict__ Wk, const float* __restrict__ bk,
    const float* __restrict__ Wv, const float* __restrict__ bv,
    const float* __restrict__ Ws, const float* __restrict__ bs,
    float* __restrict__ Q, __half* __restrict__ KV,
    float* __restrict__ S, int n) {
    if (blockIdx.x < EB) {
        int e = blockIdx.x * blockDim.x + threadIdx.x;
        if (e >= E) return;
        int d = dst[e];
        int pos = rowptr[d] + atomicAdd(&fill[d], 1);
        csrc[pos] = src[e];
        cea[pos]  = ea[e];
    } else {
        int i = (blockIdx.x - EB) * blockDim.x + threadIdx.x;
        if (i >= n * HCD) return;
        int node = i >> 7;
        int c    = i & (HCD - 1);
        float x0 = __ldg(&x[node * 2 + 0]);
        float x1 = __ldg(&x[node * 2 + 1]);
        float qv = fmaf(x0, __ldg(&Wq[c]), fmaf(x1, __ldg(&Wq[HCD + c]), __ldg(&bq[c])));
        float kv = fmaf(x0, __ldg(&Wk[c]), fmaf(x1, __ldg(&Wk[HCD + c]), __ldg(&bk[c])));
        float vv = fmaf(x0, __ldg(&Wv[c]), fmaf(x1, __ldg(&Wv[HCD + c]), __ldg(&bv[c])));
        float sv = fmaf(x0, __ldg(&Ws[c]), fmaf(x1, __ldg(&Ws[HCD + c]), __ldg(&bs[c])));
        Q[i] = qv;
        S[i] = sv;
        KV[(size_t)node * 256 + c]       = __float2half_rn(kv);
        KV[(size_t)node * 256 + 128 + c] = __float2half_rn(vv);
    }
}

// ---------------- fused single-pass edge kernel (warp per dst node) --------------
__global__ __launch_bounds__(256)
void tconv_kernel(const int* __restrict__ rowptr, const int* __restrict__ csrc,
                  const float* __restrict__ cea,
                  const float* __restrict__ Q, const __half* __restrict__ KV,
                  const float* __restrict__ We,
                  float* __restrict__ H, int n) {
    int node = (blockIdx.x * blockDim.x + threadIdx.x) >> 5;
    if (node >= n) return;
    int lane = threadIdx.x & 31;
    int r0 = __ldg(&rowptr[node]);
    int r1 = __ldg(&rowptr[node + 1]);
    int c0 = lane * 4;

    float4 q = *(const float4*)(Q + (size_t)node * HCD + c0);
    float4 w = *(const float4*)(We + c0);

    float qw = q.x * w.x + q.y * w.y + q.z * w.z + q.w * w.w;
    qw += __shfl_xor_sync(0xffffffffu, qw, 1);
    qw += __shfl_xor_sync(0xffffffffu, qw, 2);
    qw += __shfl_xor_sync(0xffffffffu, qw, 4);

    const float SC = 0.17677669529663687f;   // 1/sqrt(32)
    float den = 0.f, sev = 0.f;
    float4 acc = make_float4(0.f, 0.f, 0.f, 0.f);

    int e = r0;
    for (; e + 4 <= r1; e += 4) {
        int   s0 = __ldg(&csrc[e]),     s1 = __ldg(&csrc[e + 1]);
        int   s2 = __ldg(&csrc[e + 2]), s3 = __ldg(&csrc[e + 3]);
        float a0 = __ldg(&cea[e]),      a1 = __ldg(&cea[e + 1]);
        float a2 = __ldg(&cea[e + 2]),  a3 = __ldg(&cea[e + 3]);

        uint2 k0 = *(const uint2*)(KV + (size_t)s0 * 256 + c0);
        uint2 k1 = *(const uint2*)(KV + (size_t)s1 * 256 + c0);
        uint2 k2 = *(const uint2*)(KV + (size_t)s2 * 256 + c0);
        uint2 k3 = *(const uint2*)(KV + (size_t)s3 * 256 + c0);
        uint2 v0 = *(const uint2*)(KV + (size_t)s0 * 256 + 128 + c0);
        uint2 v1 = *(const uint2*)(KV + (size_t)s1 * 256 + 128 + c0);
        uint2 v2 = *(const uint2*)(KV + (size_t)s2 * 256 + 128 + c0);
        uint2 v3 = *(const uint2*)(KV + (size_t)s3 * 256 + 128 + c0);

        float2 kA, kB;
        kA = __half22float2(*(__half2*)&k0.x); kB = __half22float2(*(__half2*)&k0.y);
        float p0 = q.x * kA.x + q.y * kA.y + q.z * kB.x + q.w * kB.y;
        kA = __half22float2(*(__half2*)&k1.x); kB = __half22float2(*(__half2*)&k1.y);
        float p1 = q.x * kA.x + q.y * kA.y + q.z * kB.x + q.w * kB.y;
        kA = __half22float2(*(__half2*)&k2.x); kB = __half22float2(*(__half2*)&k2.y);
        float p2 = q.x * kA.x + q.y * kA.y + q.z * kB.x + q.w * kB.y;
        kA = __half22float2(*(__half2*)&k3.x); kB = __half22float2(*(__half2*)&k3.y);
        float p3 = q.x * kA.x + q.y * kA.y + q.z * kB.x + q.w * kB.y;

        p0 += __shfl_xor_sync(0xffffffffu, p0, 1);
        p1 += __shfl_xor_sync(0xffffffffu, p1, 1);
        p2 += __shfl_xor_sync(0xffffffffu, p2, 1);
        p3 += __shfl_xor_sync(0xffffffffu, p3, 1);
        p0 += __shfl_xor_sync(0xffffffffu, p0, 2);
        p1 += __shfl_xor_sync(0xffffffffu, p1, 2);
        p2 += __shfl_xor_sync(0xffffffffu, p2, 2);
        p3 += __shfl_xor_sync(0xffffffffu, p3, 2);
        p0 += __shfl_xor_sync(0xffffffffu, p0, 4);
        p1 += __shfl_xor_sync(0xffffffffu, p1, 4);
        p2 += __shfl_xor_sync(0xffffffffu, p2, 4);
        p3 += __shfl_xor_sync(0xffffffffu, p3, 4);

        float ex0 = expf((p0 + a0 * qw) * SC);
        float ex1 = expf((p1 + a1 * qw) * SC);
        float ex2 = expf((p2 + a2 * qw) * SC);
        float ex3 = expf((p3 + a3 * qw) * SC);

        den += (ex0 + ex1) + (ex2 + ex3);
        sev += (ex0 * a0 + ex1 * a1) + (ex2 * a2 + ex3 * a3);

        float2 vA, vB;
        vA = __half22float2(*(__half2*)&v0.x); vB = __half22float2(*(__half2*)&v0.y);
        acc.x = fmaf(vA.x, ex0, acc.x); acc.y = fmaf(vA.y, ex0, acc.y);
        acc.z = fmaf(vB.x, ex0, acc.z); acc.w = fmaf(vB.y, ex0, acc.w);
        vA = __half22float2(*(__half2*)&v1.x); vB = __half22float2(*(__half2*)&v1.y);
        acc.x = fmaf(vA.x, ex1, acc.x); acc.y = fmaf(vA.y, ex1, acc.y);
        acc.z = fmaf(vB.x, ex1, acc.z); acc.w = fmaf(vB.y, ex1, acc.w);
        vA = __half22float2(*(__half2*)&v2.x); vB = __half22float2(*(__half2*)&v2.y);
        acc.x = fmaf(vA.x, ex2, acc.x); acc.y = fmaf(vA.y, ex2, acc.y);
        acc.z = fmaf(vB.x, ex2, acc.z); acc.w = fmaf(vB.y, ex2, acc.w);
        vA = __half22float2(*(__half2*)&v3.x); vB = __half22float2(*(__half2*)&v3.y);
        acc.x = fmaf(vA.x, ex3, acc.x); acc.y = fmaf(vA.y, ex3, acc.y);
        acc.z = fmaf(vB.x, ex3, acc.z); acc.w = fmaf(vB.y, ex3, acc.w);
    }
    for (; e < r1; e++) {
        int   s0 = __ldg(&csrc[e]);
        float a0 = __ldg(&cea[e]);
        uint2 k0 = *(const uint2*)(KV + (size_t)s0 * 256 + c0);
        uint2 v0 = *(const uint2*)(KV + (size_t)s0 * 256 + 128 + c0);
        float2 kA = __half22float2(*(__half2*)&k0.x);
        float2 kB = __half22float2(*(__half2*)&k0.y);
        float p0 = q.x * kA.x + q.y * kA.y + q.z * kB.x + q.w * kB.y;
        p0 += __shfl_xor_sync(0xffffffffu, p0, 1);
        p0 += __shfl_xor_sync(0xffffffffu, p0, 2);
        p0 += __shfl_xor_sync(0xffffffffu, p0, 4);
        float ex0 = expf((p0 + a0 * qw) * SC);
        den += ex0;
        sev += ex0 * a0;
        float2 vA = __half22float2(*(__half2*)&v0.x);
        float2 vB = __half22float2(*(__half2*)&v0.y);
        acc.x = fmaf(vA.x, ex0, acc.x); acc.y = fmaf(vA.y, ex0, acc.y);
        acc.z = fmaf(vB.x, ex0, acc.z); acc.w = fmaf(vB.y, ex0, acc.w);
    }

    float inv = 1.f / (den + 1e-16f);
    float4 out = *(const float4*)(H + (size_t)node * HCD + c0);  // skip term
    out.x = fmaf(fmaf(sev, w.x, acc.x), inv, out.x);
    out.y = fmaf(fmaf(sev, w.y, acc.y), inv, out.y);
    out.z = fmaf(fmaf(sev, w.z, acc.z), inv, out.z);
    out.w = fmaf(fmaf(sev, w.w, acc.w), inv, out.w);
    *(float4*)(H + (size_t)node * HCD + c0) = out;
}

// ---------------- launch -----------------------------------------------------------
extern "C" void kernel_launch(void* const* d_in, const int* in_sizes, int n_in,
                              void* d_out, int out_size) {
    const float* x   = (const float*)d_in[0];
    const int*   eiw = (const int*)d_in[1];
    const float* ea  = (const float*)d_in[2];
    const float *Wq0 = (const float*)d_in[3],  *bq0 = (const float*)d_in[4];
    const float *Wk0 = (const float*)d_in[5],  *bk0 = (const float*)d_in[6];
    const float *Wv0 = (const float*)d_in[7],  *bv0 = (const float*)d_in[8];
    const float *We0 = (const float*)d_in[9];
    const float *Ws0 = (const float*)d_in[10], *bs0 = (const float*)d_in[11];
    const float *Wq1 = (const float*)d_in[12], *bq1 = (const float*)d_in[13];
    const float *Wk1 = (const float*)d_in[14], *bk1 = (const float*)d_in[15];
    const float *Wv1 = (const float*)d_in[16], *bv1 = (const float*)d_in[17];
    const float *We1 = (const float*)d_in[18];
    const float *Ws1 = (const float*)d_in[19], *bs1 = (const float*)d_in[20];
    const float *Wc1 = (const float*)d_in[21], *bc1 = (const float*)d_in[22];
    const float *Wc2 = (const float*)d_in[23], *bc2 = (const float*)d_in[24];
    const float *Wc3 = (const float*)d_in[25], *bc3 = (const float*)d_in[26];

    const int n = in_sizes[0] / 2;
    const int E = in_sizes[2];

    float *Q, *Ha, *Hb, *cea;
    __half* KV;
    int *src, *dst, *deg, *rowptr, *fill, *csrc;
    cudaGetSymbolAddress((void**)&Q,      g_Q);
    cudaGetSymbolAddress((void**)&KV,     g_KV);
    cudaGetSymbolAddress((void**)&Ha,     g_Ha);
    cudaGetSymbolAddress((void**)&Hb,     g_Hb);
    cudaGetSymbolAddress((void**)&src,    g_src);
    cudaGetSymbolAddress((void**)&dst,    g_dst);
    cudaGetSymbolAddress((void**)&deg,    g_deg);
    cudaGetSymbolAddress((void**)&rowptr, g_rowptr);
    cudaGetSymbolAddress((void**)&fill,   g_fill);
    cudaGetSymbolAddress((void**)&csrc,   g_csrc);
    cudaGetSymbolAddress((void**)&cea,    g_cea);

    const int TB = 256;
    const int EB = (E + TB - 1) / TB;
    const int NB = (n * HCD + TB - 1) / TB;
    dim3 nodeWarpGrid((n * 32 + TB - 1) / TB);
    dim3 tileGrid((n + 63) / 64);

    const int SMEM = 24576 * 4;   // 96 KB: A hi/lo (32 KB) + B hi/lo (64 KB)
    cudaFuncSetAttribute(gemm4_hmma,      cudaFuncAttributeMaxDynamicSharedMemorySize, SMEM);
    cudaFuncSetAttribute(classifier_hmma, cudaFuncAttributeMaxDynamicSharedMemorySize, SMEM);

    cudaMemsetAsync(deg,  0, (n + 1) * sizeof(int));
    cudaMemsetAsync(fill, 0, n * sizeof(int));
    convert_ei_kernel<<<EB, TB>>>(eiw, E, src, dst, deg);                         // k1
    scan_kernel<<<1, 1024>>>(deg, rowptr, n);                                      // k2
    scatter_proj0_kernel<<<EB + NB, TB>>>(src, dst, ea, rowptr, fill,              // k3
                                          csrc, cea, E, EB,
                                          x, Wq0, bq0, Wk0, bk0, Wv0, bv0,
                                          Ws0, bs0, Q, KV, Ha, n);
    tconv_kernel<<<nodeWarpGrid, TB>>>(rowptr, csrc, cea, Q, KV, We0, Ha, n);     // k4 <- profiled
    gemm4_hmma<<<tileGrid, 128, SMEM>>>(Ha,                                        // k5
                                        Wq1, bq1, Q,
                                        Wk1, bk1,
                                        Wv1, bv1, KV,
                                        Ws1, bs1, Hb, n);
    tconv_kernel<<<nodeWarpGrid, TB>>>(rowptr, csrc, cea, Q, KV, We1, Hb, n);     // k6
    classifier_hmma<<<tileGrid, 128, SMEM>>>(Hb, Wc1, bc1, Wc2, bc2, Wc3, bc3,     // k7
                                             (float*)d_out, n);
}

// round 11
// speedup vs baseline: 2.2425x; 1.1167x over previous
#include <cuda_runtime.h>
#include <cuda_fp16.h>
#include <cstdint>
#include <math.h>

#define NMAX 100000
#define EMAX 800000
#define HCD  128     // H*C = 4*32
#define NH   4       // heads

// ---------------- scratch ----------------------------------------------------
__device__ float  g_Q [(size_t)NMAX * HCD];       // Q
__device__ __half g_KV[(size_t)NMAX * 2 * HCD];   // per node: 128 K halfs, 128 V halfs
__device__ float  g_Ha[(size_t)NMAX * HCD];       // layer0 out
__device__ float  g_Hb[(size_t)NMAX * HCD];       // layer1 out
__device__ int    g_src[EMAX];
__device__ int    g_dst[EMAX];
__device__ int    g_deg[NMAX + 1];
__device__ int    g_rowptr[NMAX + 1];
__device__ int    g_fill[NMAX];
__device__ int    g_csrc[EMAX];
__device__ float  g_cea[EMAX];

// ---------------- fp16 HMMA helpers ------------------------------------------
// smem word offsets (uint32 units) for M=128 tiles
#define A_HI_W 0
#define A_LO_W 8192
#define B_HI_W 16384
// B_LO offset = B_HI_W + 8*JT*64

__device__ __forceinline__ void mma_f16(float* c, const uint32_t* a, const uint32_t* b) {
    asm volatile(
        "mma.sync.aligned.m16n8k16.row.col.f32.f16.f16.f32 "
        "{%0,%1,%2,%3}, {%4,%5,%6,%7}, {%8,%9}, {%0,%1,%2,%3};"
        : "+f"(c[0]), "+f"(c[1]), "+f"(c[2]), "+f"(c[3])
        : "r"(a[0]), "r"(a[1]), "r"(a[2]), "r"(a[3]), "r"(b[0]), "r"(b[1]));
}

__device__ __forceinline__ uint32_t packh2(__half a, __half b) {
    __half2 h = __halves2half2(a, b);
    return *(uint32_t*)&h;
}

// ---- fill A: 128 rows x 128 k, fp16 hi/lo split, m16n8k16 fragment order -------
// 256 threads.
template<bool RIN>
__device__ __forceinline__ void fillA(uint32_t* smw, const float* __restrict__ X,
                                      int node0, int n, int tid) {
#pragma unroll
    for (int it = 0; it < 8; it++) {
        int cid = it * 256 + tid;          // 0..2047
        int row = cid >> 4;                // 0..127
        int k0  = (cid & 15) << 3;         // 0..120 step 8
        int node = node0 + row;
        float4 a = make_float4(0.f, 0.f, 0.f, 0.f), b = a;
        if (node < n) {
            const float4* xp = (const float4*)(X + (size_t)node * 128 + k0);
            a = xp[0]; b = xp[1];
        }
        if (RIN) {
            a.x = fmaxf(a.x, 0.f); a.y = fmaxf(a.y, 0.f);
            a.z = fmaxf(a.z, 0.f); a.w = fmaxf(a.w, 0.f);
            b.x = fmaxf(b.x, 0.f); b.y = fmaxf(b.y, 0.f);
            b.z = fmaxf(b.z, 0.f); b.w = fmaxf(b.w, 0.f);
        }
        float v[8] = {a.x, a.y, a.z, a.w, b.x, b.y, b.z, b.w};
        __half hh[8], hl[8];
#pragma unroll
        for (int j = 0; j < 8; j++) {
            hh[j] = __float2half_rn(v[j]);
            hl[j] = __float2half_rn(v[j] - __half2float(hh[j]));
        }
        int w = row >> 4, r = row & 15;
        int s = k0 >> 4;
        int kk8 = (k0 >> 3) & 1;
        int reg = (r >> 3) + 2 * kk8;
        int lane0 = (r & 7) * 4;
        int base = ((w * 8 + s) * 32 + lane0) * 4 + reg;
#pragma unroll
        for (int p = 0; p < 4; p++) {
            smw[A_HI_W + base + p * 4] = packh2(hh[2 * p], hh[2 * p + 1]);
            smw[A_LO_W + base + p * 4] = packh2(hl[2 * p], hl[2 * p + 1]);
        }
    }
}

// ---- fill B: W[128,NC] -> col-major fragments; optional lo plane ----------------
template<int NC, bool LO>
__device__ __forceinline__ void fillB(uint32_t* smw, const float* __restrict__ W, int tid) {
    constexpr int JT = NC / 8;
    constexpr int BLO = B_HI_W + 8 * JT * 64;
#pragma unroll
    for (int it = 0; it < NC / 16; it++) {
        int cid = it * 256 + tid;          // 0..16*NC-1
        int nr = cid & (NC - 1);
        int kc = cid / NC;                 // 0..15
        int k0 = kc << 3;
        float v[8];
#pragma unroll
        for (int j = 0; j < 8; j++) v[j] = __ldg(&W[(size_t)(k0 + j) * NC + nr]);
        __half hh[8];
#pragma unroll
        for (int j = 0; j < 8; j++) hh[j] = __float2half_rn(v[j]);
        int j = nr >> 3, nn = nr & 7;
        int s = k0 >> 4;
        int reg = (k0 >> 3) & 1;
        int lane0 = nn * 4;
        int base = ((s * JT + j) * 32 + lane0) * 2 + reg;
#pragma unroll
        for (int p = 0; p < 4; p++)
            smw[B_HI_W + base + p * 2] = packh2(hh[2 * p], hh[2 * p + 1]);
        if (LO) {
            __half hl[8];
#pragma unroll
            for (int j2 = 0; j2 < 8; j2++)
                hl[j2] = __float2half_rn(v[j2] - __half2float(hh[j2]));
#pragma unroll
            for (int p = 0; p < 4; p++)
                smw[BLO + base + p * 2] = packh2(hl[2 * p], hl[2 * p + 1]);
        }
    }
}

// ---- split MMA compute: TERMS=2 -> (Ahi+Alo)xBhi ; TERMS=3 adds AhixBlo ---------
template<int JT, int TERMS>
__device__ __forceinline__ void computeTile(const uint32_t* smw, float acc[][4],
                                            int wid, int lane) {
    constexpr int BLO = B_HI_W + 8 * JT * 64;
#pragma unroll
    for (int s = 0; s < 8; s++) {
        uint4 ah4 = *(const uint4*)&smw[A_HI_W + ((wid * 8 + s) * 32 + lane) * 4];
        uint4 al4 = *(const uint4*)&smw[A_LO_W + ((wid * 8 + s) * 32 + lane) * 4];
        uint32_t ah[4] = {ah4.x, ah4.y, ah4.z, ah4.w};
        uint32_t al[4] = {al4.x, al4.y, al4.z, al4.w};
#pragma unroll
        for (int j = 0; j < JT; j++) {
            uint2 bh2 = *(const uint2*)&smw[B_HI_W + ((s * JT + j) * 32 + lane) * 2];
            uint32_t bh[2] = {bh2.x, bh2.y};
            mma_f16(acc[j], ah, bh);
            mma_f16(acc[j], al, bh);
            if (TERMS == 3) {
                uint2 bl2 = *(const uint2*)&smw[BLO + ((s * JT + j) * 32 + lane) * 2];
                uint32_t bl[2] = {bl2.x, bl2.y};
                mma_f16(acc[j], ah, bl);
            }
        }
    }
}

// ---- store a value pair back into A fragments (for fused classifier) -----------
__device__ __forceinline__ void storeZfrag(uint32_t* smw, int lrow, int col,
                                           float v0, float v1) {
    int w = lrow >> 4, r = lrow & 15;
    int s = col >> 4, kk = col & 15;
    int reg = (r >> 3) + 2 * (kk >> 3);
    int lane = (r & 7) * 4 + ((kk & 7) >> 1);
    int idx = ((w * 8 + s) * 32 + lane) * 4 + reg;
    __half h0 = __float2half_rn(v0), h1 = __float2half_rn(v1);
    smw[A_HI_W + idx] = packh2(h0, h1);
    __half l0 = __float2half_rn(v0 - __half2float(h0));
    __half l1 = __float2half_rn(v1 - __half2float(h1));
    smw[A_LO_W + idx] = packh2(l0, l1);
}

// ---------------- fused 4-projection GEMM (layer 1), fp16 HMMA -------------------
// Q/K/V: 2-term split (B-lo skipped).  S (skip path): 3-term.
__global__ __launch_bounds__(256)
void gemm4_hmma(const float* __restrict__ X,
                const float* __restrict__ W0, const float* __restrict__ b0, float* __restrict__ Q,
                const float* __restrict__ W1, const float* __restrict__ b1,
                const float* __restrict__ W2, const float* __restrict__ b2, __half* __restrict__ KV,
                const float* __restrict__ W3, const float* __restrict__ b3, float* __restrict__ S,
                int n) {
    extern __shared__ uint32_t smw[];
    const int tid = threadIdx.x, wid = tid >> 5, lane = tid & 31;
    const int node0 = blockIdx.x * 128;

    fillA<true>(smw, X, node0, n, tid);

    const float* Wm[4] = {W0, W1, W2, W3};
    const float* bm[4] = {b0, b1, b2, b3};

    int row0 = node0 + wid * 16 + (lane >> 2);
    int row1 = row0 + 8;

    for (int m = 0; m < 4; m++) {
        __syncthreads();               // prior compute done with B region (and A ready)
        if (m == 3) fillB<128, true >(smw, Wm[m], tid);
        else        fillB<128, false>(smw, Wm[m], tid);
        __syncthreads();

        float acc[16][4];
#pragma unroll
        for (int j = 0; j < 16; j++) {
            float bb0 = __ldg(&bm[m][j * 8 + (lane & 3) * 2]);
            float bb1 = __ldg(&bm[m][j * 8 + (lane & 3) * 2 + 1]);
            acc[j][0] = bb0; acc[j][1] = bb1; acc[j][2] = bb0; acc[j][3] = bb1;
        }
        if (m == 3) computeTile<16, 3>(smw, acc, wid, lane);
        else        computeTile<16, 2>(smw, acc, wid, lane);

        if (m == 0 || m == 3) {
            float* Y = (m == 0) ? Q : S;
#pragma unroll
            for (int j = 0; j < 16; j++) {
                int col = j * 8 + (lane & 3) * 2;
                if (row0 < n) *(float2*)(Y + (size_t)row0 * 128 + col) = make_float2(acc[j][0], acc[j][1]);
                if (row1 < n) *(float2*)(Y + (size_t)row1 * 128 + col) = make_float2(acc[j][2], acc[j][3]);
            }
        } else {
            int off = (m == 1) ? 0 : 128;
#pragma unroll
            for (int j = 0; j < 16; j++) {
                int col = j * 8 + (lane & 3) * 2;
                if (row0 < n) *(__half2*)(KV + (size_t)row0 * 256 + off + col) = __floats2half2_rn(acc[j][0], acc[j][1]);
                if (row1 < n) *(__half2*)(KV + (size_t)row1 * 256 + off + col) = __floats2half2_rn(acc[j][2], acc[j][3]);
            }
        }
    }
}

// ---------------- fused classifier: relu(Hb)@Wc1 ->relu-> @Wc2 ->relu-> @Wc3 -----
__global__ __launch_bounds__(256)
void classifier_hmma(const float* __restrict__ X,
                     const float* __restrict__ Wc1, const float* __restrict__ bc1,
                     const float* __restrict__ Wc2, const float* __restrict__ bc2,
                     const float* __restrict__ Wc3, const float* __restrict__ bc3,
                     float* __restrict__ out, int n) {
    extern __shared__ uint32_t smw[];
    const int tid = threadIdx.x, wid = tid >> 5, lane = tid & 31;
    const int node0 = blockIdx.x * 128;

    fillA<true>(smw, X, node0, n, tid);
    fillB<128, true>(smw, Wc1, tid);
    __syncthreads();

    // stage 1: Z1 = relu(X @ Wc1 + bc1), 128 cols
    float acc[16][4];
#pragma unroll
    for (int j = 0; j < 16; j++) {
        float bb0 = __ldg(&bc1[j * 8 + (lane & 3) * 2]);
        float bb1 = __ldg(&bc1[j * 8 + (lane & 3) * 2 + 1]);
        acc[j][0] = bb0; acc[j][1] = bb1; acc[j][2] = bb0; acc[j][3] = bb1;
    }
    computeTile<16, 3>(smw, acc, wid, lane);

    {
        int lr0 = wid * 16 + (lane >> 2);
        int lr1 = lr0 + 8;
#pragma unroll
        for (int j = 0; j < 16; j++) {
            int col = j * 8 + (lane & 3) * 2;
            storeZfrag(smw, lr0, col, fmaxf(acc[j][0], 0.f), fmaxf(acc[j][1], 0.f));
            storeZfrag(smw, lr1, col, fmaxf(acc[j][2], 0.f), fmaxf(acc[j][3], 0.f));
        }
    }
    __syncthreads();
    fillB<64, true>(smw, Wc2, tid);
    __syncthreads();

    // stage 2: Z2 = relu(Z1 @ Wc2 + bc2), 64 cols
    float acc2[8][4];
#pragma unroll
    for (int j = 0; j < 8; j++) {
        float bb0 = __ldg(&bc2[j * 8 + (lane & 3) * 2]);
        float bb1 = __ldg(&bc2[j * 8 + (lane & 3) * 2 + 1]);
        acc2[j][0] = bb0; acc2[j][1] = bb1; acc2[j][2] = bb0; acc2[j][3] = bb1;
    }
    computeTile<8, 3>(smw, acc2, wid, lane);

    // stage 3: out = relu(Z2) @ Wc3 + bc3
    float p0 = 0.f, p1 = 0.f;
#pragma unroll
    for (int j = 0; j < 8; j++) {
        int c = j * 8 + (lane & 3) * 2;
        float w0 = __ldg(&Wc3[c]), w1 = __ldg(&Wc3[c + 1]);
        p0 += fmaxf(acc2[j][0], 0.f) * w0 + fmaxf(acc2[j][1], 0.f) * w1;
        p1 += fmaxf(acc2[j][2], 0.f) * w0 + fmaxf(acc2[j][3], 0.f) * w1;
    }
    p0 += __shfl_xor_sync(0xffffffffu, p0, 1);
    p0 += __shfl_xor_sync(0xffffffffu, p0, 2);
    p1 += __shfl_xor_sync(0xffffffffu, p1, 1);
    p1 += __shfl_xor_sync(0xffffffffu, p1, 2);

    if ((lane & 3) == 0) {
        float bv = __ldg(&bc3[0]);
        int row0 = node0 + wid * 16 + (lane >> 2);
        int row1 = row0 + 8;
        if (row0 < n) out[row0] = p0 + bv;
        if (row1 < n) out[row1] = p1 + bv;
    }
}

// ---------------- edge_index normalization + degree histogram -------------------
__global__ void convert_ei_kernel(const int* __restrict__ p, int E,
                                  int* __restrict__ src, int* __restrict__ dst,
                                  int* __restrict__ deg) {
    __shared__ int s_is64;
    if (threadIdx.x == 0) {
        int is64 = 1;
        for (int i = 0; i < 64; i++)
            if (p[2 * i + 1] != 0) { is64 = 0; break; }
        s_is64 = is64;
    }
    __syncthreads();
    const int is64 = s_is64;
    int e = blockIdx.x * blockDim.x + threadIdx.x;
    if (e >= E) return;
    int s, d;
    if (is64) { s = p[2 * e]; d = p[2 * (E + e)]; }
    else      { s = p[e];     d = p[E + e]; }
    src[e] = s; dst[e] = d;
    atomicAdd(&deg[d], 1);
}

// ---------------- single-block exclusive scan over degrees ----------------------
__global__ void scan_kernel(const int* __restrict__ deg, int* __restrict__ rowptr, int n) {
    __shared__ int sm[1024];
    int tid = threadIdx.x;
    int chunk = (n + 1023) >> 10;
    int start = tid * chunk;
    int end = min(start + chunk, n);
    int sum = 0;
    for (int i = start; i < end; i++) sum += deg[i];
    sm[tid] = sum;
    __syncthreads();
    for (int d = 1; d < 1024; d <<= 1) {
        int v = (tid >= d) ? sm[tid - d] : 0;
        __syncthreads();
        sm[tid] += v;
        __syncthreads();
    }
    int off = sm[tid] - sum;   // exclusive
    for (int i = start; i < end; i++) { rowptr[i] = off; off += deg[i]; }
    if (tid == 1023) rowptr[n] = off;
}

// ---------------- fused scatter (CSR) + layer-0 projection ----------------------
__global__ void scatter_proj0_kernel(
    const int* __restrict__ src, const int* __restrict__ dst,
    const float* __restrict__ ea,
    const int* __restrict__ rowptr, int* __restrict__ fill,
    int* __restrict__ csrc, float* __restrict__ cea, int E, int EB,
    const float* __restrict__ x,
    const float* __restrict__ Wq, const float* __restrict__ bq,
    const float* __restrict__ Wk, const float* __restrict__ bk,
    const float* __restrict__ Wv, const float* __restrict__ bv,
    const float* __restrict__ Ws, const float* __restrict__ bs,
    float* __restrict__ Q, __half* __restrict__ KV,
    float* __restrict__ S, int n) {
    if (blockIdx.x < EB) {
        int e = blockIdx.x * blockDim.x + threadIdx.x;
        if (e >= E) return;
        int d = dst[e];
        int pos = rowptr[d] + atomicAdd(&fill[d], 1);
        csrc[pos] = src[e];
        cea[pos]  = ea[e];
    } else {
        int i = (blockIdx.x - EB) * blockDim.x + threadIdx.x;
        if (i >= n * HCD) return;
        int node = i >> 7;
        int c    = i & (HCD - 1);
        float x0 = __ldg(&x[node * 2 + 0]);
        float x1 = __ldg(&x[node * 2 + 1]);
        float qv = fmaf(x0, __ldg(&Wq[c]), fmaf(x1, __ldg(&Wq[HCD + c]), __ldg(&bq[c])));
        float kv = fmaf(x0, __ldg(&Wk[c]), fmaf(x1, __ldg(&Wk[HCD + c]), __ldg(&bk[c])));
        float vv = fmaf(x0, __ldg(&Wv[c]), fmaf(x1, __ldg(&Wv[HCD + c]), __ldg(&bv[c])));
        float sv = fmaf(x0, __ldg(&Ws[c]), fmaf(x1, __ldg(&Ws[HCD + c]), __ldg(&bs[c])));
        Q[i] = qv;
        S[i] = sv;
        KV[(size_t)node * 256 + c]       = __float2half_rn(kv);
        KV[(size_t)node * 256 + 128 + c] = __float2half_rn(vv);
    }
}

// ---------------- fused single-pass edge kernel (warp per dst node) --------------
__global__ __launch_bounds__(256)
void tconv_kernel(const int* __restrict__ rowptr, const int* __restrict__ csrc,
                  const float* __restrict__ cea,
                  const float* __restrict__ Q, const __half* __restrict__ KV,
                  const float* __restrict__ We,
                  float* __restrict__ H, int n) {
    int node = (blockIdx.x * blockDim.x + threadIdx.x) >> 5;
    if (node >= n) return;
    int lane = threadIdx.x & 31;
    int r0 = __ldg(&rowptr[node]);
    int r1 = __ldg(&rowptr[node + 1]);
    int c0 = lane * 4;

    float4 q = *(const float4*)(Q + (size_t)node * HCD + c0);
    float4 w = *(const float4*)(We + c0);

    float qw = q.x * w.x + q.y * w.y + q.z * w.z + q.w * w.w;
    qw += __shfl_xor_sync(0xffffffffu, qw, 1);
    qw += __shfl_xor_sync(0xffffffffu, qw, 2);
    qw += __shfl_xor_sync(0xffffffffu, qw, 4);

    const float SC = 0.17677669529663687f;   // 1/sqrt(32)
    float den = 0.f, sev = 0.f;
    float4 acc = make_float4(0.f, 0.f, 0.f, 0.f);

    int e = r0;
    for (; e + 4 <= r1; e += 4) {
        int   s0 = __ldg(&csrc[e]),     s1 = __ldg(&csrc[e + 1]);
        int   s2 = __ldg(&csrc[e + 2]), s3 = __ldg(&csrc[e + 3]);
        float a0 = __ldg(&cea[e]),      a1 = __ldg(&cea[e + 1]);
        float a2 = __ldg(&cea[e + 2]),  a3 = __ldg(&cea[e + 3]);

        uint2 k0 = *(const uint2*)(KV + (size_t)s0 * 256 + c0);
        uint2 k1 = *(const uint2*)(KV + (size_t)s1 * 256 + c0);
        uint2 k2 = *(const uint2*)(KV + (size_t)s2 * 256 + c0);
        uint2 k3 = *(const uint2*)(KV + (size_t)s3 * 256 + c0);
        uint2 v0 = *(const uint2*)(KV + (size_t)s0 * 256 + 128 + c0);
        uint2 v1 = *(const uint2*)(KV + (size_t)s1 * 256 + 128 + c0);
        uint2 v2 = *(const uint2*)(KV + (size_t)s2 * 256 + 128 + c0);
        uint2 v3 = *(const uint2*)(KV + (size_t)s3 * 256 + 128 + c0);

        float2 kA, kB;
        kA = __half22float2(*(__half2*)&k0.x); kB = __half22float2(*(__half2*)&k0.y);
        float p0 = q.x * kA.x + q.y * kA.y + q.z * kB.x + q.w * kB.y;
        kA = __half22float2(*(__half2*)&k1.x); kB = __half22float2(*(__half2*)&k1.y);
        float p1 = q.x * kA.x + q.y * kA.y + q.z * kB.x + q.w * kB.y;
        kA = __half22float2(*(__half2*)&k2.x); kB = __half22float2(*(__half2*)&k2.y);
        float p2 = q.x * kA.x + q.y * kA.y + q.z * kB.x + q.w * kB.y;
        kA = __half22float2(*(__half2*)&k3.x); kB = __half22float2(*(__half2*)&k3.y);
        float p3 = q.x * kA.x + q.y * kA.y + q.z * kB.x + q.w * kB.y;

        p0 += __shfl_xor_sync(0xffffffffu, p0, 1);
        p1 += __shfl_xor_sync(0xffffffffu, p1, 1);
        p2 += __shfl_xor_sync(0xffffffffu, p2, 1);
        p3 += __shfl_xor_sync(0xffffffffu, p3, 1);
        p0 += __shfl_xor_sync(0xffffffffu, p0, 2);
        p1 += __shfl_xor_sync(0xffffffffu, p1, 2);
        p2 += __shfl_xor_sync(0xffffffffu, p2, 2);
        p3 += __shfl_xor_sync(0xffffffffu, p3, 2);
        p0 += __shfl_xor_sync(0xffffffffu, p0, 4);
        p1 += __shfl_xor_sync(0xffffffffu, p1, 4);
        p2 += __shfl_xor_sync(0xffffffffu, p2, 4);
        p3 += __shfl_xor_sync(0xffffffffu, p3, 4);

        float ex0 = expf((p0 + a0 * qw) * SC);
        float ex1 = expf((p1 + a1 * qw) * SC);
        float ex2 = expf((p2 + a2 * qw) * SC);
        float ex3 = expf((p3 + a3 * qw) * SC);

        den += (ex0 + ex1) + (ex2 + ex3);
        sev += (ex0 * a0 + ex1 * a1) + (ex2 * a2 + ex3 * a3);

        float2 vA, vB;
        vA = __half22float2(*(__half2*)&v0.x); vB = __half22float2(*(__half2*)&v0.y);
        acc.x = fmaf(vA.x, ex0, acc.x); acc.y = fmaf(vA.y, ex0, acc.y);
        acc.z = fmaf(vB.x, ex0, acc.z); acc.w = fmaf(vB.y, ex0, acc.w);
        vA = __half22float2(*(__half2*)&v1.x); vB = __half22float2(*(__half2*)&v1.y);
        acc.x = fmaf(vA.x, ex1, acc.x); acc.y = fmaf(vA.y, ex1, acc.y);
        acc.z = fmaf(vB.x, ex1, acc.z); acc.w = fmaf(vB.y, ex1, acc.w);
        vA = __half22float2(*(__half2*)&v2.x); vB = __half22float2(*(__half2*)&v2.y);
        acc.x = fmaf(vA.x, ex2, acc.x); acc.y = fmaf(vA.y, ex2, acc.y);
        acc.z = fmaf(vB.x, ex2, acc.z); acc.w = fmaf(vB.y, ex2, acc.w);
        vA = __half22float2(*(__half2*)&v3.x); vB = __half22float2(*(__half2*)&v3.y);
        acc.x = fmaf(vA.x, ex3, acc.x); acc.y = fmaf(vA.y, ex3, acc.y);
        acc.z = fmaf(vB.x, ex3, acc.z); acc.w = fmaf(vB.y, ex3, acc.w);
    }
    for (; e < r1; e++) {
        int   s0 = __ldg(&csrc[e]);
        float a0 = __ldg(&cea[e]);
        uint2 k0 = *(const uint2*)(KV + (size_t)s0 * 256 + c0);
        uint2 v0 = *(const uint2*)(KV + (size_t)s0 * 256 + 128 + c0);
        float2 kA = __half22float2(*(__half2*)&k0.x);
        float2 kB = __half22float2(*(__half2*)&k0.y);
        float p0 = q.x * kA.x + q.y * kA.y + q.z * kB.x + q.w * kB.y;
        p0 += __shfl_xor_sync(0xffffffffu, p0, 1);
        p0 += __shfl_xor_sync(0xffffffffu, p0, 2);
        p0 += __shfl_xor_sync(0xffffffffu, p0, 4);
        float ex0 = expf((p0 + a0 * qw) * SC);
        den += ex0;
        sev += ex0 * a0;
        float2 vA = __half22float2(*(__half2*)&v0.x);
        float2 vB = __half22float2(*(__half2*)&v0.y);
        acc.x = fmaf(vA.x, ex0, acc.x); acc.y = fmaf(vA.y, ex0, acc.y);
        acc.z = fmaf(vB.x, ex0, acc.z); acc.w = fmaf(vB.y, ex0, acc.w);
    }

    float inv = 1.f / (den + 1e-16f);
    float4 out = *(const float4*)(H + (size_t)node * HCD + c0);  // skip term
    out.x = fmaf(fmaf(sev, w.x, acc.x), inv, out.x);
    out.y = fmaf(fmaf(sev, w.y, acc.y), inv, out.y);
    out.z = fmaf(fmaf(sev, w.z, acc.z), inv, out.z);
    out.w = fmaf(fmaf(sev, w.w, acc.w), inv, out.w);
    *(float4*)(H + (size_t)node * HCD + c0) = out;
}

// ---------------- launch -----------------------------------------------------------
extern "C" void kernel_launch(void* const* d_in, const int* in_sizes, int n_in,
                              void* d_out, int out_size) {
    const float* x   = (const float*)d_in[0];
    const int*   eiw = (const int*)d_in[1];
    const float* ea  = (const float*)d_in[2];
    const float *Wq0 = (const float*)d_in[3],  *bq0 = (const float*)d_in[4];
    const float *Wk0 = (const float*)d_in[5],  *bk0 = (const float*)d_in[6];
    const float *Wv0 = (const float*)d_in[7],  *bv0 = (const float*)d_in[8];
    const float *We0 = (const float*)d_in[9];
    const float *Ws0 = (const float*)d_in[10], *bs0 = (const float*)d_in[11];
    const float *Wq1 = (const float*)d_in[12], *bq1 = (const float*)d_in[13];
    const float *Wk1 = (const float*)d_in[14], *bk1 = (const float*)d_in[15];
    const float *Wv1 = (const float*)d_in[16], *bv1 = (const float*)d_in[17];
    const float *We1 = (const float*)d_in[18];
    const float *Ws1 = (const float*)d_in[19], *bs1 = (const float*)d_in[20];
    const float *Wc1 = (const float*)d_in[21], *bc1 = (const float*)d_in[22];
    const float *Wc2 = (const float*)d_in[23], *bc2 = (const float*)d_in[24];
    const float *Wc3 = (const float*)d_in[25], *bc3 = (const float*)d_in[26];

    const int n = in_sizes[0] / 2;
    const int E = in_sizes[2];

    float *Q, *Ha, *Hb, *cea;
    __half* KV;
    int *src, *dst, *deg, *rowptr, *fill, *csrc;
    cudaGetSymbolAddress((void**)&Q,      g_Q);
    cudaGetSymbolAddress((void**)&KV,     g_KV);
    cudaGetSymbolAddress((void**)&Ha,     g_Ha);
    cudaGetSymbolAddress((void**)&Hb,     g_Hb);
    cudaGetSymbolAddress((void**)&src,    g_src);
    cudaGetSymbolAddress((void**)&dst,    g_dst);
    cudaGetSymbolAddress((void**)&deg,    g_deg);
    cudaGetSymbolAddress((void**)&rowptr, g_rowptr);
    cudaGetSymbolAddress((void**)&fill,   g_fill);
    cudaGetSymbolAddress((void**)&csrc,   g_csrc);
    cudaGetSymbolAddress((void**)&cea,    g_cea);

    const int TB = 256;
    const int EB = (E + TB - 1) / TB;
    const int NB = (n * HCD + TB - 1) / TB;
    dim3 nodeWarpGrid((n * 32 + TB - 1) / TB);
    dim3 tileGrid((n + 127) / 128);

    const int SMEM = 32768 * 4;   // 128 KB: A hi/lo (64 KB) + B hi/lo (64 KB)
    cudaFuncSetAttribute(gemm4_hmma,      cudaFuncAttributeMaxDynamicSharedMemorySize, SMEM);
    cudaFuncSetAttribute(classifier_hmma, cudaFuncAttributeMaxDynamicSharedMemorySize, SMEM);

    cudaMemsetAsync(deg,  0, (n + 1) * sizeof(int));
    cudaMemsetAsync(fill, 0, n * sizeof(int));
    convert_ei_kernel<<<EB, TB>>>(eiw, E, src, dst, deg);                         // k1
    scan_kernel<<<1, 1024>>>(deg, rowptr, n);                                      // k2
    scatter_proj0_kernel<<<EB + NB, TB>>>(src, dst, ea, rowptr, fill,              // k3
                                          csrc, cea, E, EB,
                                          x, Wq0, bq0, Wk0, bk0, Wv0, bv0,
                                          Ws0, bs0, Q, KV, Ha, n);
    tconv_kernel<<<nodeWarpGrid, TB>>>(rowptr, csrc, cea, Q, KV, We0, Ha, n);     // k4 <- profiled
    gemm4_hmma<<<tileGrid, 256, SMEM>>>(Ha,                                        // k5
                                        Wq1, bq1, Q,
                                        Wk1, bk1,
                                        Wv1, bv1, KV,
                                        Ws1, bs1, Hb, n);
    tconv_kernel<<<nodeWarpGrid, TB>>>(rowptr, csrc, cea, Q, KV, We1, Hb, n);     // k6
    classifier_hmma<<<tileGrid, 256, SMEM>>>(Hb, Wc1, bc1, Wc2, bc2, Wc3, bc3,     // k7
                                             (float*)d_out, n);
}

// round 12
// speedup vs baseline: 2.4735x; 1.1030x over previous
#include <cuda_runtime.h>
#include <cuda_fp16.h>
#include <cstdint>
#include <math.h>

#define NMAX 100000
#define EMAX 800000
#define HCD  128     // H*C = 4*32
#define NH   4       // heads

// ---------------- scratch ----------------------------------------------------
__device__ float  g_Q [(size_t)NMAX * HCD];       // Q (layer 1)
__device__ __half g_KV[(size_t)NMAX * 2 * HCD];   // per node: 128 K halfs, 128 V halfs (layer 1)
__device__ float  g_Ha[(size_t)NMAX * HCD];       // layer0 out
__device__ float  g_Hb[(size_t)NMAX * HCD];       // layer1 out
__device__ int    g_src[EMAX];
__device__ int    g_dst[EMAX];
__device__ int    g_deg[NMAX + 1];
__device__ int    g_rowptr[NMAX + 1];
__device__ int    g_fill[NMAX];
__device__ int    g_csrc[EMAX];
__device__ float  g_cea[EMAX];

// ---------------- fp16 HMMA helpers ------------------------------------------
// smem word offsets (uint32 units): A hi/lo 32KB each, one 32KB B plane
#define A_HI_W 0
#define A_LO_W 8192
#define B_HI_W 16384
// single-pass lo plane (only for JT<=8): BLO = B_HI_W + 8*JT*64

__device__ __forceinline__ void mma_f16(float* c, const uint32_t* a, const uint32_t* b) {
    asm volatile(
        "mma.sync.aligned.m16n8k16.row.col.f32.f16.f16.f32 "
        "{%0,%1,%2,%3}, {%4,%5,%6,%7}, {%8,%9}, {%0,%1,%2,%3};"
        : "+f"(c[0]), "+f"(c[1]), "+f"(c[2]), "+f"(c[3])
        : "r"(a[0]), "r"(a[1]), "r"(a[2]), "r"(a[3]), "r"(b[0]), "r"(b[1]));
}

__device__ __forceinline__ uint32_t packh2(__half a, __half b) {
    __half2 h = __halves2half2(a, b);
    return *(uint32_t*)&h;
}

// ---- fill A: 128 rows x 128 k, fp16 hi/lo split, m16n8k16 fragment order -------
template<bool RIN>
__device__ __forceinline__ void fillA(uint32_t* smw, const float* __restrict__ X,
                                      int node0, int n, int tid) {
#pragma unroll
    for (int it = 0; it < 8; it++) {
        int cid = it * 256 + tid;
        int row = cid >> 4;
        int k0  = (cid & 15) << 3;
        int node = node0 + row;
        float4 a = make_float4(0.f, 0.f, 0.f, 0.f), b = a;
        if (node < n) {
            const float4* xp = (const float4*)(X + (size_t)node * 128 + k0);
            a = xp[0]; b = xp[1];
        }
        if (RIN) {
            a.x = fmaxf(a.x, 0.f); a.y = fmaxf(a.y, 0.f);
            a.z = fmaxf(a.z, 0.f); a.w = fmaxf(a.w, 0.f);
            b.x = fmaxf(b.x, 0.f); b.y = fmaxf(b.y, 0.f);
            b.z = fmaxf(b.z, 0.f); b.w = fmaxf(b.w, 0.f);
        }
        float v[8] = {a.x, a.y, a.z, a.w, b.x, b.y, b.z, b.w};
        __half hh[8], hl[8];
#pragma unroll
        for (int j = 0; j < 8; j++) {
            hh[j] = __float2half_rn(v[j]);
            hl[j] = __float2half_rn(v[j] - __half2float(hh[j]));
        }
        int w = row >> 4, r = row & 15;
        int s = k0 >> 4;
        int kk8 = (k0 >> 3) & 1;
        int reg = (r >> 3) + 2 * kk8;
        int lane0 = (r & 7) * 4;
        int base = ((w * 8 + s) * 32 + lane0) * 4 + reg;
#pragma unroll
        for (int p = 0; p < 4; p++) {
            smw[A_HI_W + base + p * 4] = packh2(hh[2 * p], hh[2 * p + 1]);
            smw[A_LO_W + base + p * 4] = packh2(hl[2 * p], hl[2 * p + 1]);
        }
    }
}

// ---- fill B: W[128,NC] -> col-major fragments -----------------------------------
// PLANE 0: hi -> B_HI_W ; PLANE 1: lo -> B_HI_W (two-pass) ; PLANE 2: hi + lo@BLO
template<int NC, int PLANE>
__device__ __forceinline__ void fillB(uint32_t* smw, const float* __restrict__ W, int tid) {
    constexpr int JT = NC / 8;
    constexpr int BLO = B_HI_W + 8 * JT * 64;
#pragma unroll
    for (int it = 0; it < NC / 16; it++) {
        int cid = it * 256 + tid;
        int nr = cid & (NC - 1);
        int kc = cid / NC;
        int k0 = kc << 3;
        float v[8];
#pragma unroll
        for (int j = 0; j < 8; j++) v[j] = __ldg(&W[(size_t)(k0 + j) * NC + nr]);
        __half hh[8];
#pragma unroll
        for (int j = 0; j < 8; j++) hh[j] = __float2half_rn(v[j]);
        int j = nr >> 3, nn = nr & 7;
        int s = k0 >> 4;
        int reg = (k0 >> 3) & 1;
        int lane0 = nn * 4;
        int base = ((s * JT + j) * 32 + lane0) * 2 + reg;
        if (PLANE == 0 || PLANE == 2) {
#pragma unroll
            for (int p = 0; p < 4; p++)
                smw[B_HI_W + base + p * 2] = packh2(hh[2 * p], hh[2 * p + 1]);
        }
        if (PLANE == 1 || PLANE == 2) {
            __half hl[8];
#pragma unroll
            for (int j2 = 0; j2 < 8; j2++)
                hl[j2] = __float2half_rn(v[j2] - __half2float(hh[j2]));
            int dstw = (PLANE == 1) ? B_HI_W : BLO;
#pragma unroll
            for (int p = 0; p < 4; p++)
                smw[dstw + base + p * 2] = packh2(hl[2 * p], hl[2 * p + 1]);
        }
    }
}

// ---- split MMA compute -----------------------------------------------------------
// TERMS 1: Ahi x B@B_HI_W ; TERMS 2: (Ahi+Alo) x B@B_HI_W ; TERMS 3: 2 + Ahi x B@BLO
template<int JT, int TERMS>
__device__ __forceinline__ void computeTile(const uint32_t* smw, float acc[][4],
                                            int wid, int lane) {
    constexpr int BLO = B_HI_W + 8 * JT * 64;
#pragma unroll
    for (int s = 0; s < 8; s++) {
        uint4 ah4 = *(const uint4*)&smw[A_HI_W + ((wid * 8 + s) * 32 + lane) * 4];
        uint32_t ah[4] = {ah4.x, ah4.y, ah4.z, ah4.w};
        uint32_t al[4];
        if (TERMS >= 2) {
            uint4 al4 = *(const uint4*)&smw[A_LO_W + ((wid * 8 + s) * 32 + lane) * 4];
            al[0] = al4.x; al[1] = al4.y; al[2] = al4.z; al[3] = al4.w;
        }
#pragma unroll
        for (int j = 0; j < JT; j++) {
            uint2 bh2 = *(const uint2*)&smw[B_HI_W + ((s * JT + j) * 32 + lane) * 2];
            uint32_t bh[2] = {bh2.x, bh2.y};
            mma_f16(acc[j], ah, bh);
            if (TERMS >= 2) mma_f16(acc[j], al, bh);
            if (TERMS == 3) {
                uint2 bl2 = *(const uint2*)&smw[BLO + ((s * JT + j) * 32 + lane) * 2];
                uint32_t bl[2] = {bl2.x, bl2.y};
                mma_f16(acc[j], ah, bl);
            }
        }
    }
}

// ---- store a value pair back into A fragments (for fused classifier) -----------
__device__ __forceinline__ void storeZfrag(uint32_t* smw, int lrow, int col,
                                           float v0, float v1) {
    int w = lrow >> 4, r = lrow & 15;
    int s = col >> 4, kk = col & 15;
    int reg = (r >> 3) + 2 * (kk >> 3);
    int lane = (r & 7) * 4 + ((kk & 7) >> 1);
    int idx = ((w * 8 + s) * 32 + lane) * 4 + reg;
    __half h0 = __float2half_rn(v0), h1 = __float2half_rn(v1);
    smw[A_HI_W + idx] = packh2(h0, h1);
    __half l0 = __float2half_rn(v0 - __half2float(h0));
    __half l1 = __float2half_rn(v1 - __half2float(h1));
    smw[A_LO_W + idx] = packh2(l0, l1);
}

// ---------------- fused 4-projection GEMM (layer 1), fp16 HMMA -------------------
// Q/K/V: 2-term split. S (skip path): 3-term via two-pass B fill.
__global__ __launch_bounds__(256, 2)
void gemm4_hmma(const float* __restrict__ X,
                const float* __restrict__ W0, const float* __restrict__ b0, float* __restrict__ Q,
                const float* __restrict__ W1, const float* __restrict__ b1,
                const float* __restrict__ W2, const float* __restrict__ b2, __half* __restrict__ KV,
                const float* __restrict__ W3, const float* __restrict__ b3, float* __restrict__ S,
                int n) {
    extern __shared__ uint32_t smw[];
    const int tid = threadIdx.x, wid = tid >> 5, lane = tid & 31;
    const int node0 = blockIdx.x * 128;

    fillA<true>(smw, X, node0, n, tid);

    const float* Wm[4] = {W0, W1, W2, W3};
    const float* bm[4] = {b0, b1, b2, b3};

    int row0 = node0 + wid * 16 + (lane >> 2);
    int row1 = row0 + 8;

    for (int m = 0; m < 4; m++) {
        __syncthreads();
        fillB<128, 0>(smw, Wm[m], tid);
        __syncthreads();

        float acc[16][4];
#pragma unroll
        for (int j = 0; j < 16; j++) {
            float bb0 = __ldg(&bm[m][j * 8 + (lane & 3) * 2]);
            float bb1 = __ldg(&bm[m][j * 8 + (lane & 3) * 2 + 1]);
            acc[j][0] = bb0; acc[j][1] = bb1; acc[j][2] = bb0; acc[j][3] = bb1;
        }
        computeTile<16, 2>(smw, acc, wid, lane);

        if (m == 3) {   // skip path gets the 3rd term via second B pass
            __syncthreads();
            fillB<128, 1>(smw, Wm[m], tid);
            __syncthreads();
            computeTile<16, 1>(smw, acc, wid, lane);
        }

        if (m == 0 || m == 3) {
            float* Y = (m == 0) ? Q : S;
#pragma unroll
            for (int j = 0; j < 16; j++) {
                int col = j * 8 + (lane & 3) * 2;
                if (row0 < n) *(float2*)(Y + (size_t)row0 * 128 + col) = make_float2(acc[j][0], acc[j][1]);
                if (row1 < n) *(float2*)(Y + (size_t)row1 * 128 + col) = make_float2(acc[j][2], acc[j][3]);
            }
        } else {
            int off = (m == 1) ? 0 : 128;
#pragma unroll
            for (int j = 0; j < 16; j++) {
                int col = j * 8 + (lane & 3) * 2;
                if (row0 < n) *(__half2*)(KV + (size_t)row0 * 256 + off + col) = __floats2half2_rn(acc[j][0], acc[j][1]);
                if (row1 < n) *(__half2*)(KV + (size_t)row1 * 256 + off + col) = __floats2half2_rn(acc[j][2], acc[j][3]);
            }
        }
    }
}

// ---------------- fused classifier ------------------------------------------------
__global__ __launch_bounds__(256, 2)
void classifier_hmma(const float* __restrict__ X,
                     const float* __restrict__ Wc1, const float* __restrict__ bc1,
                     const float* __restrict__ Wc2, const float* __restrict__ bc2,
                     const float* __restrict__ Wc3, const float* __restrict__ bc3,
                     float* __restrict__ out, int n) {
    extern __shared__ uint32_t smw[];
    const int tid = threadIdx.x, wid = tid >> 5, lane = tid & 31;
    const int node0 = blockIdx.x * 128;

    fillA<true>(smw, X, node0, n, tid);
    fillB<128, 0>(smw, Wc1, tid);
    __syncthreads();

    // stage 1: Z1 = relu(X @ Wc1 + bc1) — 3-term via two-pass B
    float acc[16][4];
#pragma unroll
    for (int j = 0; j < 16; j++) {
        float bb0 = __ldg(&bc1[j * 8 + (lane & 3) * 2]);
        float bb1 = __ldg(&bc1[j * 8 + (lane & 3) * 2 + 1]);
        acc[j][0] = bb0; acc[j][1] = bb1; acc[j][2] = bb0; acc[j][3] = bb1;
    }
    computeTile<16, 2>(smw, acc, wid, lane);
    __syncthreads();
    fillB<128, 1>(smw, Wc1, tid);
    __syncthreads();
    computeTile<16, 1>(smw, acc, wid, lane);
    __syncthreads();   // done reading A before overwriting with Z1

    {
        int lr0 = wid * 16 + (lane >> 2);
        int lr1 = lr0 + 8;
#pragma unroll
        for (int j = 0; j < 16; j++) {
            int col = j * 8 + (lane & 3) * 2;
            storeZfrag(smw, lr0, col, fmaxf(acc[j][0], 0.f), fmaxf(acc[j][1], 0.f));
            storeZfrag(smw, lr1, col, fmaxf(acc[j][2], 0.f), fmaxf(acc[j][3], 0.f));
        }
    }
    __syncthreads();
    fillB<64, 2>(smw, Wc2, tid);   // hi + lo planes (fits for NC=64)
    __syncthreads();

    // stage 2: Z2 = relu(Z1 @ Wc2 + bc2), 64 cols, single-pass 3-term
    float acc2[8][4];
#pragma unroll
    for (int j = 0; j < 8; j++) {
        float bb0 = __ldg(&bc2[j * 8 + (lane & 3) * 2]);
        float bb1 = __ldg(&bc2[j * 8 + (lane & 3) * 2 + 1]);
        acc2[j][0] = bb0; acc2[j][1] = bb1; acc2[j][2] = bb0; acc2[j][3] = bb1;
    }
    computeTile<8, 3>(smw, acc2, wid, lane);

    // stage 3: out = relu(Z2) @ Wc3 + bc3
    float p0 = 0.f, p1 = 0.f;
#pragma unroll
    for (int j = 0; j < 8; j++) {
        int c = j * 8 + (lane & 3) * 2;
        float w0 = __ldg(&Wc3[c]), w1 = __ldg(&Wc3[c + 1]);
        p0 += fmaxf(acc2[j][0], 0.f) * w0 + fmaxf(acc2[j][1], 0.f) * w1;
        p1 += fmaxf(acc2[j][2], 0.f) * w0 + fmaxf(acc2[j][3], 0.f) * w1;
    }
    p0 += __shfl_xor_sync(0xffffffffu, p0, 1);
    p0 += __shfl_xor_sync(0xffffffffu, p0, 2);
    p1 += __shfl_xor_sync(0xffffffffu, p1, 1);
    p1 += __shfl_xor_sync(0xffffffffu, p1, 2);

    if ((lane & 3) == 0) {
        float bv = __ldg(&bc3[0]);
        int row0 = node0 + wid * 16 + (lane >> 2);
        int row1 = row0 + 8;
        if (row0 < n) out[row0] = p0 + bv;
        if (row1 < n) out[row1] = p1 + bv;
    }
}

// ---------------- edge_index normalization + degree histogram -------------------
__global__ void convert_ei_kernel(const int* __restrict__ p, int E,
                                  int* __restrict__ src, int* __restrict__ dst,
                                  int* __restrict__ deg) {
    __shared__ int s_is64;
    if (threadIdx.x == 0) {
        int is64 = 1;
        for (int i = 0; i < 64; i++)
            if (p[2 * i + 1] != 0) { is64 = 0; break; }
        s_is64 = is64;
    }
    __syncthreads();
    const int is64 = s_is64;
    int e = blockIdx.x * blockDim.x + threadIdx.x;
    if (e >= E) return;
    int s, d;
    if (is64) { s = p[2 * e]; d = p[2 * (E + e)]; }
    else      { s = p[e];     d = p[E + e]; }
    src[e] = s; dst[e] = d;
    atomicAdd(&deg[d], 1);
}

// ---------------- single-block exclusive scan over degrees ----------------------
__global__ void scan_kernel(const int* __restrict__ deg, int* __restrict__ rowptr, int n) {
    __shared__ int sm[1024];
    int tid = threadIdx.x;
    int chunk = (n + 1023) >> 10;
    int start = tid * chunk;
    int end = min(start + chunk, n);
    int sum = 0;
    for (int i = start; i < end; i++) sum += deg[i];
    sm[tid] = sum;
    __syncthreads();
    for (int d = 1; d < 1024; d <<= 1) {
        int v = (tid >= d) ? sm[tid - d] : 0;
        __syncthreads();
        sm[tid] += v;
        __syncthreads();
    }
    int off = sm[tid] - sum;   // exclusive
    for (int i = start; i < end; i++) { rowptr[i] = off; off += deg[i]; }
    if (tid == 1023) rowptr[n] = off;
}

// ---------------- scatter edges into CSR order -----------------------------------
__global__ void scatter_kernel(const int* __restrict__ src, const int* __restrict__ dst,
                               const float* __restrict__ ea,
                               const int* __restrict__ rowptr, int* __restrict__ fill,
                               int* __restrict__ csrc, float* __restrict__ cea, int E) {
    int e = blockIdx.x * blockDim.x + threadIdx.x;
    if (e >= E) return;
    int d = dst[e];
    int pos = rowptr[d] + atomicAdd(&fill[d], 1);
    csrc[pos] = src[e];
    cea[pos]  = ea[e];
}

// ---------------- layer-0 fused tconv (weights inlined; no proj0 needed) ---------
// k[src] = x[src]@Wk+bk computed on the fly (input dim 2); same for v, q, skip.
__global__ __launch_bounds__(256)
void tconv0_kernel(const int* __restrict__ rowptr, const int* __restrict__ csrc,
                   const float* __restrict__ cea, const float* __restrict__ x,
                   const float* __restrict__ Wq, const float* __restrict__ bq,
                   const float* __restrict__ Wk, const float* __restrict__ bk,
                   const float* __restrict__ Wv, const float* __restrict__ bv,
                   const float* __restrict__ Ws, const float* __restrict__ bs,
                   const float* __restrict__ We,
                   float* __restrict__ H, int n) {
    int node = (blockIdx.x * blockDim.x + threadIdx.x) >> 5;
    if (node >= n) return;
    int lane = threadIdx.x & 31;
    int c0 = lane * 4;
    int r0 = __ldg(&rowptr[node]);
    int r1 = __ldg(&rowptr[node + 1]);

    float4 wk0 = *(const float4*)(Wk + c0);
    float4 wk1 = *(const float4*)(Wk + HCD + c0);
    float4 bkv = *(const float4*)(bk + c0);
    float4 wv0 = *(const float4*)(Wv + c0);
    float4 wv1 = *(const float4*)(Wv + HCD + c0);
    float4 bvv = *(const float4*)(bv + c0);
    float4 w   = *(const float4*)(We + c0);

    float2 xn = *(const float2*)(x + 2 * (size_t)node);
    float4 q;
    {
        float4 wq0 = *(const float4*)(Wq + c0);
        float4 wq1 = *(const float4*)(Wq + HCD + c0);
        float4 bqv = *(const float4*)(bq + c0);
        q.x = fmaf(xn.x, wq0.x, fmaf(xn.y, wq1.x, bqv.x));
        q.y = fmaf(xn.x, wq0.y, fmaf(xn.y, wq1.y, bqv.y));
        q.z = fmaf(xn.x, wq0.z, fmaf(xn.y, wq1.z, bqv.z));
        q.w = fmaf(xn.x, wq0.w, fmaf(xn.y, wq1.w, bqv.w));
    }

    float qw = q.x * w.x + q.y * w.y + q.z * w.z + q.w * w.w;
    qw += __shfl_xor_sync(0xffffffffu, qw, 1);
    qw += __shfl_xor_sync(0xffffffffu, qw, 2);
    qw += __shfl_xor_sync(0xffffffffu, qw, 4);

    const float SC = 0.17677669529663687f;   // 1/sqrt(32)
    float den = 0.f, sev = 0.f;
    float4 acc = make_float4(0.f, 0.f, 0.f, 0.f);

    int e = r0;
    for (; e + 2 <= r1; e += 2) {
        int   s0 = __ldg(&csrc[e]),  s1 = __ldg(&csrc[e + 1]);
        float a0 = __ldg(&cea[e]),   a1 = __ldg(&cea[e + 1]);
        float2 x0 = __ldg((const float2*)(x + 2 * (size_t)s0));
        float2 x1 = __ldg((const float2*)(x + 2 * (size_t)s1));

        float p0 = q.x * fmaf(x0.x, wk0.x, fmaf(x0.y, wk1.x, bkv.x))
                 + q.y * fmaf(x0.x, wk0.y, fmaf(x0.y, wk1.y, bkv.y))
                 + q.z * fmaf(x0.x, wk0.z, fmaf(x0.y, wk1.z, bkv.z))
                 + q.w * fmaf(x0.x, wk0.w, fmaf(x0.y, wk1.w, bkv.w));
        float p1 = q.x * fmaf(x1.x, wk0.x, fmaf(x1.y, wk1.x, bkv.x))
                 + q.y * fmaf(x1.x, wk0.y, fmaf(x1.y, wk1.y, bkv.y))
                 + q.z * fmaf(x1.x, wk0.z, fmaf(x1.y, wk1.z, bkv.z))
                 + q.w * fmaf(x1.x, wk0.w, fmaf(x1.y, wk1.w, bkv.w));

        p0 += __shfl_xor_sync(0xffffffffu, p0, 1);
        p1 += __shfl_xor_sync(0xffffffffu, p1, 1);
        p0 += __shfl_xor_sync(0xffffffffu, p0, 2);
        p1 += __shfl_xor_sync(0xffffffffu, p1, 2);
        p0 += __shfl_xor_sync(0xffffffffu, p0, 4);
        p1 += __shfl_xor_sync(0xffffffffu, p1, 4);

        float ex0 = expf((p0 + a0 * qw) * SC);
        float ex1 = expf((p1 + a1 * qw) * SC);
        den += ex0 + ex1;
        sev += ex0 * a0 + ex1 * a1;

        acc.x = fmaf(fmaf(x0.x, wv0.x, fmaf(x0.y, wv1.x, bvv.x)), ex0,
                fmaf(fmaf(x1.x, wv0.x, fmaf(x1.y, wv1.x, bvv.x)), ex1, acc.x));
        acc.y = fmaf(fmaf(x0.x, wv0.y, fmaf(x0.y, wv1.y, bvv.y)), ex0,
                fmaf(fmaf(x1.x, wv0.y, fmaf(x1.y, wv1.y, bvv.y)), ex1, acc.y));
        acc.z = fmaf(fmaf(x0.x, wv0.z, fmaf(x0.y, wv1.z, bvv.z)), ex0,
                fmaf(fmaf(x1.x, wv0.z, fmaf(x1.y, wv1.z, bvv.z)), ex1, acc.z));
        acc.w = fmaf(fmaf(x0.x, wv0.w, fmaf(x0.y, wv1.w, bvv.w)), ex0,
                fmaf(fmaf(x1.x, wv0.w, fmaf(x1.y, wv1.w, bvv.w)), ex1, acc.w));
    }
    for (; e < r1; e++) {
        int   s0 = __ldg(&csrc[e]);
        float a0 = __ldg(&cea[e]);
        float2 x0 = __ldg((const float2*)(x + 2 * (size_t)s0));
        float p0 = q.x * fmaf(x0.x, wk0.x, fmaf(x0.y, wk1.x, bkv.x))
                 + q.y * fmaf(x0.x, wk0.y, fmaf(x0.y, wk1.y, bkv.y))
                 + q.z * fmaf(x0.x, wk0.z, fmaf(x0.y, wk1.z, bkv.z))
                 + q.w * fmaf(x0.x, wk0.w, fmaf(x0.y, wk1.w, bkv.w));
        p0 += __shfl_xor_sync(0xffffffffu, p0, 1);
        p0 += __shfl_xor_sync(0xffffffffu, p0, 2);
        p0 += __shfl_xor_sync(0xffffffffu, p0, 4);
        float ex0 = expf((p0 + a0 * qw) * SC);
        den += ex0;
        sev += ex0 * a0;
        acc.x = fmaf(fmaf(x0.x, wv0.x, fmaf(x0.y, wv1.x, bvv.x)), ex0, acc.x);
        acc.y = fmaf(fmaf(x0.x, wv0.y, fmaf(x0.y, wv1.y, bvv.y)), ex0, acc.y);
        acc.z = fmaf(fmaf(x0.x, wv0.z, fmaf(x0.y, wv1.z, bvv.z)), ex0, acc.z);
        acc.w = fmaf(fmaf(x0.x, wv0.w, fmaf(x0.y, wv1.w, bvv.w)), ex0, acc.w);
    }

    float inv = 1.f / (den + 1e-16f);
    float4 ws0 = *(const float4*)(Ws + c0);
    float4 ws1 = *(const float4*)(Ws + HCD + c0);
    float4 bsv = *(const float4*)(bs + c0);
    float4 out;
    out.x = fmaf(xn.x, ws0.x, fmaf(xn.y, ws1.x, bsv.x)) + fmaf(sev, w.x, acc.x) * inv;
    out.y = fmaf(xn.x, ws0.y, fmaf(xn.y, ws1.y, bsv.y)) + fmaf(sev, w.y, acc.y) * inv;
    out.z = fmaf(xn.x, ws0.z, fmaf(xn.y, ws1.z, bsv.z)) + fmaf(sev, w.z, acc.z) * inv;
    out.w = fmaf(xn.x, ws0.w, fmaf(xn.y, ws1.w, bsv.w)) + fmaf(sev, w.w, acc.w) * inv;
    *(float4*)(H + (size_t)node * HCD + c0) = out;
}

// ---------------- layer-1 fused edge kernel (fp16 KV gather) ---------------------
__global__ __launch_bounds__(256)
void tconv_kernel(const int* __restrict__ rowptr, const int* __restrict__ csrc,
                  const float* __restrict__ cea,
                  const float* __restrict__ Q, const __half* __restrict__ KV,
                  const float* __restrict__ We,
                  float* __restrict__ H, int n) {
    int node = (blockIdx.x * blockDim.x + threadIdx.x) >> 5;
    if (node >= n) return;
    int lane = threadIdx.x & 31;
    int r0 = __ldg(&rowptr[node]);
    int r1 = __ldg(&rowptr[node + 1]);
    int c0 = lane * 4;

    float4 q = *(const float4*)(Q + (size_t)node * HCD + c0);
    float4 w = *(const float4*)(We + c0);

    float qw = q.x * w.x + q.y * w.y + q.z * w.z + q.w * w.w;
    qw += __shfl_xor_sync(0xffffffffu, qw, 1);
    qw += __shfl_xor_sync(0xffffffffu, qw, 2);
    qw += __shfl_xor_sync(0xffffffffu, qw, 4);

    const float SC = 0.17677669529663687f;
    float den = 0.f, sev = 0.f;
    float4 acc = make_float4(0.f, 0.f, 0.f, 0.f);

    int e = r0;
    for (; e + 4 <= r1; e += 4) {
        int   s0 = __ldg(&csrc[e]),     s1 = __ldg(&csrc[e + 1]);
        int   s2 = __ldg(&csrc[e + 2]), s3 = __ldg(&csrc[e + 3]);
        float a0 = __ldg(&cea[e]),      a1 = __ldg(&cea[e + 1]);
        float a2 = __ldg(&cea[e + 2]),  a3 = __ldg(&cea[e + 3]);

        uint2 k0 = *(const uint2*)(KV + (size_t)s0 * 256 + c0);
        uint2 k1 = *(const uint2*)(KV + (size_t)s1 * 256 + c0);
        uint2 k2 = *(const uint2*)(KV + (size_t)s2 * 256 + c0);
        uint2 k3 = *(const uint2*)(KV + (size_t)s3 * 256 + c0);
        uint2 v0 = *(const uint2*)(KV + (size_t)s0 * 256 + 128 + c0);
        uint2 v1 = *(const uint2*)(KV + (size_t)s1 * 256 + 128 + c0);
        uint2 v2 = *(const uint2*)(KV + (size_t)s2 * 256 + 128 + c0);
        uint2 v3 = *(const uint2*)(KV + (size_t)s3 * 256 + 128 + c0);

        float2 kA, kB;
        kA = __half22float2(*(__half2*)&k0.x); kB = __half22float2(*(__half2*)&k0.y);
        float p0 = q.x * kA.x + q.y * kA.y + q.z * kB.x + q.w * kB.y;
        kA = __half22float2(*(__half2*)&k1.x); kB = __half22float2(*(__half2*)&k1.y);
        float p1 = q.x * kA.x + q.y * kA.y + q.z * kB.x + q.w * kB.y;
        kA = __half22float2(*(__half2*)&k2.x); kB = __half22float2(*(__half2*)&k2.y);
        float p2 = q.x * kA.x + q.y * kA.y + q.z * kB.x + q.w * kB.y;
        kA = __half22float2(*(__half2*)&k3.x); kB = __half22float2(*(__half2*)&k3.y);
        float p3 = q.x * kA.x + q.y * kA.y + q.z * kB.x + q.w * kB.y;

        p0 += __shfl_xor_sync(0xffffffffu, p0, 1);
        p1 += __shfl_xor_sync(0xffffffffu, p1, 1);
        p2 += __shfl_xor_sync(0xffffffffu, p2, 1);
        p3 += __shfl_xor_sync(0xffffffffu, p3, 1);
        p0 += __shfl_xor_sync(0xffffffffu, p0, 2);
        p1 += __shfl_xor_sync(0xffffffffu, p1, 2);
        p2 += __shfl_xor_sync(0xffffffffu, p2, 2);
        p3 += __shfl_xor_sync(0xffffffffu, p3, 2);
        p0 += __shfl_xor_sync(0xffffffffu, p0, 4);
        p1 += __shfl_xor_sync(0xffffffffu, p1, 4);
        p2 += __shfl_xor_sync(0xffffffffu, p2, 4);
        p3 += __shfl_xor_sync(0xffffffffu, p3, 4);

        float ex0 = expf((p0 + a0 * qw) * SC);
        float ex1 = expf((p1 + a1 * qw) * SC);
        float ex2 = expf((p2 + a2 * qw) * SC);
        float ex3 = expf((p3 + a3 * qw) * SC);

        den += (ex0 + ex1) + (ex2 + ex3);
        sev += (ex0 * a0 + ex1 * a1) + (ex2 * a2 + ex3 * a3);

        float2 vA, vB;
        vA = __half22float2(*(__half2*)&v0.x); vB = __half22float2(*(__half2*)&v0.y);
        acc.x = fmaf(vA.x, ex0, acc.x); acc.y = fmaf(vA.y, ex0, acc.y);
        acc.z = fmaf(vB.x, ex0, acc.z); acc.w = fmaf(vB.y, ex0, acc.w);
        vA = __half22float2(*(__half2*)&v1.x); vB = __half22float2(*(__half2*)&v1.y);
        acc.x = fmaf(vA.x, ex1, acc.x); acc.y = fmaf(vA.y, ex1, acc.y);
        acc.z = fmaf(vB.x, ex1, acc.z); acc.w = fmaf(vB.y, ex1, acc.w);
        vA = __half22float2(*(__half2*)&v2.x); vB = __half22float2(*(__half2*)&v2.y);
        acc.x = fmaf(vA.x, ex2, acc.x); acc.y = fmaf(vA.y, ex2, acc.y);
        acc.z = fmaf(vB.x, ex2, acc.z); acc.w = fmaf(vB.y, ex2, acc.w);
        vA = __half22float2(*(__half2*)&v3.x); vB = __half22float2(*(__half2*)&v3.y);
        acc.x = fmaf(vA.x, ex3, acc.x); acc.y = fmaf(vA.y, ex3, acc.y);
        acc.z = fmaf(vB.x, ex3, acc.z); acc.w = fmaf(vB.y, ex3, acc.w);
    }
    for (; e < r1; e++) {
        int   s0 = __ldg(&csrc[e]);
        float a0 = __ldg(&cea[e]);
        uint2 k0 = *(const uint2*)(KV + (size_t)s0 * 256 + c0);
        uint2 v0 = *(const uint2*)(KV + (size_t)s0 * 256 + 128 + c0);
        float2 kA = __half22float2(*(__half2*)&k0.x);
        float2 kB = __half22float2(*(__half2*)&k0.y);
        float p0 = q.x * kA.x + q.y * kA.y + q.z * kB.x + q.w * kB.y;
        p0 += __shfl_xor_sync(0xffffffffu, p0, 1);
        p0 += __shfl_xor_sync(0xffffffffu, p0, 2);
        p0 += __shfl_xor_sync(0xffffffffu, p0, 4);
        float ex0 = expf((p0 + a0 * qw) * SC);
        den += ex0;
        sev += ex0 * a0;
        float2 vA = __half22float2(*(__half2*)&v0.x);
        float2 vB = __half22float2(*(__half2*)&v0.y);
        acc.x = fmaf(vA.x, ex0, acc.x); acc.y = fmaf(vA.y, ex0, acc.y);
        acc.z = fmaf(vB.x, ex0, acc.z); acc.w = fmaf(vB.y, ex0, acc.w);
    }

    float inv = 1.f / (den + 1e-16f);
    float4 out = *(const float4*)(H + (size_t)node * HCD + c0);  // skip term
    out.x = fmaf(fmaf(sev, w.x, acc.x), inv, out.x);
    out.y = fmaf(fmaf(sev, w.y, acc.y), inv, out.y);
    out.z = fmaf(fmaf(sev, w.z, acc.z), inv, out.z);
    out.w = fmaf(fmaf(sev, w.w, acc.w), inv, out.w);
    *(float4*)(H + (size_t)node * HCD + c0) = out;
}

// ---------------- launch -----------------------------------------------------------
extern "C" void kernel_launch(void* const* d_in, const int* in_sizes, int n_in,
                              void* d_out, int out_size) {
    const float* x   = (const float*)d_in[0];
    const int*   eiw = (const int*)d_in[1];
    const float* ea  = (const float*)d_in[2];
    const float *Wq0 = (const float*)d_in[3],  *bq0 = (const float*)d_in[4];
    const float *Wk0 = (const float*)d_in[5],  *bk0 = (const float*)d_in[6];
    const float *Wv0 = (const float*)d_in[7],  *bv0 = (const float*)d_in[8];
    const float *We0 = (const float*)d_in[9];
    const float *Ws0 = (const float*)d_in[10], *bs0 = (const float*)d_in[11];
    const float *Wq1 = (const float*)d_in[12], *bq1 = (const float*)d_in[13];
    const float *Wk1 = (const float*)d_in[14], *bk1 = (const float*)d_in[15];
    const float *Wv1 = (const float*)d_in[16], *bv1 = (const float*)d_in[17];
    const float *We1 = (const float*)d_in[18];
    const float *Ws1 = (const float*)d_in[19], *bs1 = (const float*)d_in[20];
    const float *Wc1 = (const float*)d_in[21], *bc1 = (const float*)d_in[22];
    const float *Wc2 = (const float*)d_in[23], *bc2 = (const float*)d_in[24];
    const float *Wc3 = (const float*)d_in[25], *bc3 = (const float*)d_in[26];

    const int n = in_sizes[0] / 2;
    const int E = in_sizes[2];

    float *Q, *Ha, *Hb, *cea;
    __half* KV;
    int *src, *dst, *deg, *rowptr, *fill, *csrc;
    cudaGetSymbolAddress((void**)&Q,      g_Q);
    cudaGetSymbolAddress((void**)&KV,     g_KV);
    cudaGetSymbolAddress((void**)&Ha,     g_Ha);
    cudaGetSymbolAddress((void**)&Hb,     g_Hb);
    cudaGetSymbolAddress((void**)&src,    g_src);
    cudaGetSymbolAddress((void**)&dst,    g_dst);
    cudaGetSymbolAddress((void**)&deg,    g_deg);
    cudaGetSymbolAddress((void**)&rowptr, g_rowptr);
    cudaGetSymbolAddress((void**)&fill,   g_fill);
    cudaGetSymbolAddress((void**)&csrc,   g_csrc);
    cudaGetSymbolAddress((void**)&cea,    g_cea);

    const int TB = 256;
    const int EB = (E + TB - 1) / TB;
    dim3 nodeWarpGrid((n * 32 + TB - 1) / TB);
    dim3 tileGrid((n + 127) / 128);

    const int SMEM = 24576 * 4;   // 96 KB: A hi/lo (64 KB) + B plane (32 KB)
    cudaFuncSetAttribute(gemm4_hmma,      cudaFuncAttributeMaxDynamicSharedMemorySize, SMEM);
    cudaFuncSetAttribute(classifier_hmma, cudaFuncAttributeMaxDynamicSharedMemorySize, SMEM);

    cudaMemsetAsync(deg,  0, (n + 1) * sizeof(int));
    cudaMemsetAsync(fill, 0, n * sizeof(int));
    convert_ei_kernel<<<EB, TB>>>(eiw, E, src, dst, deg);                          // k1
    scan_kernel<<<1, 1024>>>(deg, rowptr, n);                                       // k2
    scatter_kernel<<<EB, TB>>>(src, dst, ea, rowptr, fill, csrc, cea, E);           // k3
    tconv0_kernel<<<nodeWarpGrid, TB>>>(rowptr, csrc, cea, x,                       // k4 <- profiled
                                        Wq0, bq0, Wk0, bk0, Wv0, bv0, Ws0, bs0,
                                        We0, Ha, n);
    gemm4_hmma<<<tileGrid, 256, SMEM>>>(Ha,                                         // k5
                                        Wq1, bq1, Q,
                                        Wk1, bk1,
                                        Wv1, bv1, KV,
                                        Ws1, bs1, Hb, n);
    tconv_kernel<<<nodeWarpGrid, TB>>>(rowptr, csrc, cea, Q, KV, We1, Hb, n);      // k6
    classifier_hmma<<<tileGrid, 256, SMEM>>>(Hb, Wc1, bc1, Wc2, bc2, Wc3, bc3,      // k7
                                             (float*)d_out, n);
}

// round 13
// speedup vs baseline: 2.7420x; 1.1085x over previous
#include <cuda_runtime.h>
#include <cuda_fp16.h>
#include <cstdint>
#include <math.h>

#define NMAX 100000
#define EMAX 800000
#define HCD  128     // H*C = 4*32
#define NH   4       // heads

// ---------------- scratch ----------------------------------------------------
__device__ float  g_Q [(size_t)NMAX * HCD];       // Q (layer 1)
__device__ __half g_KV[(size_t)NMAX * 2 * HCD];   // per node: 128 K halfs, 128 V halfs (layer 1)
__device__ float  g_Ha[(size_t)NMAX * HCD];       // layer0 out
__device__ float  g_Hb[(size_t)NMAX * HCD];       // layer1 out
__device__ int    g_src[EMAX];
__device__ int    g_dst[EMAX];
__device__ int    g_deg[NMAX + 1];
__device__ int    g_rowptr[NMAX + 1];
__device__ int    g_fill[NMAX];
__device__ int    g_csrc[EMAX];
__device__ float  g_cea[EMAX];

// ---------------- fp16 HMMA helpers ------------------------------------------
#define A_HI_W 0
#define A_LO_W 8192
#define B_HI_W 16384

__device__ __forceinline__ void mma_f16(float* c, const uint32_t* a, const uint32_t* b) {
    asm volatile(
        "mma.sync.aligned.m16n8k16.row.col.f32.f16.f16.f32 "
        "{%0,%1,%2,%3}, {%4,%5,%6,%7}, {%8,%9}, {%0,%1,%2,%3};"
        : "+f"(c[0]), "+f"(c[1]), "+f"(c[2]), "+f"(c[3])
        : "r"(a[0]), "r"(a[1]), "r"(a[2]), "r"(a[3]), "r"(b[0]), "r"(b[1]));
}

__device__ __forceinline__ uint32_t packh2(__half a, __half b) {
    __half2 h = __halves2half2(a, b);
    return *(uint32_t*)&h;
}

template<bool RIN>
__device__ __forceinline__ void fillA(uint32_t* smw, const float* __restrict__ X,
                                      int node0, int n, int tid) {
#pragma unroll
    for (int it = 0; it < 8; it++) {
        int cid = it * 256 + tid;
        int row = cid >> 4;
        int k0  = (cid & 15) << 3;
        int node = node0 + row;
        float4 a = make_float4(0.f, 0.f, 0.f, 0.f), b = a;
        if (node < n) {
            const float4* xp = (const float4*)(X + (size_t)node * 128 + k0);
            a = xp[0]; b = xp[1];
        }
        if (RIN) {
            a.x = fmaxf(a.x, 0.f); a.y = fmaxf(a.y, 0.f);
            a.z = fmaxf(a.z, 0.f); a.w = fmaxf(a.w, 0.f);
            b.x = fmaxf(b.x, 0.f); b.y = fmaxf(b.y, 0.f);
            b.z = fmaxf(b.z, 0.f); b.w = fmaxf(b.w, 0.f);
        }
        float v[8] = {a.x, a.y, a.z, a.w, b.x, b.y, b.z, b.w};
        __half hh[8], hl[8];
#pragma unroll
        for (int j = 0; j < 8; j++) {
            hh[j] = __float2half_rn(v[j]);
            hl[j] = __float2half_rn(v[j] - __half2float(hh[j]));
        }
        int w = row >> 4, r = row & 15;
        int s = k0 >> 4;
        int kk8 = (k0 >> 3) & 1;
        int reg = (r >> 3) + 2 * kk8;
        int lane0 = (r & 7) * 4;
        int base = ((w * 8 + s) * 32 + lane0) * 4 + reg;
#pragma unroll
        for (int p = 0; p < 4; p++) {
            smw[A_HI_W + base + p * 4] = packh2(hh[2 * p], hh[2 * p + 1]);
            smw[A_LO_W + base + p * 4] = packh2(hl[2 * p], hl[2 * p + 1]);
        }
    }
}

template<int NC, int PLANE>
__device__ __forceinline__ void fillB(uint32_t* smw, const float* __restrict__ W, int tid) {
    constexpr int JT = NC / 8;
    constexpr int BLO = B_HI_W + 8 * JT * 64;
#pragma unroll
    for (int it = 0; it < NC / 16; it++) {
        int cid = it * 256 + tid;
        int nr = cid & (NC - 1);
        int kc = cid / NC;
        int k0 = kc << 3;
        float v[8];
#pragma unroll
        for (int j = 0; j < 8; j++) v[j] = __ldg(&W[(size_t)(k0 + j) * NC + nr]);
        __half hh[8];
#pragma unroll
        for (int j = 0; j < 8; j++) hh[j] = __float2half_rn(v[j]);
        int j = nr >> 3, nn = nr & 7;
        int s = k0 >> 4;
        int reg = (k0 >> 3) & 1;
        int lane0 = nn * 4;
        int base = ((s * JT + j) * 32 + lane0) * 2 + reg;
        if (PLANE == 0 || PLANE == 2) {
#pragma unroll
            for (int p = 0; p < 4; p++)
                smw[B_HI_W + base + p * 2] = packh2(hh[2 * p], hh[2 * p + 1]);
        }
        if (PLANE == 1 || PLANE == 2) {
            __half hl[8];
#pragma unroll
            for (int j2 = 0; j2 < 8; j2++)
                hl[j2] = __float2half_rn(v[j2] - __half2float(hh[j2]));
            int dstw = (PLANE == 1) ? B_HI_W : BLO;
#pragma unroll
            for (int p = 0; p < 4; p++)
                smw[dstw + base + p * 2] = packh2(hl[2 * p], hl[2 * p + 1]);
        }
    }
}

template<int JT, int TERMS>
__device__ __forceinline__ void computeTile(const uint32_t* smw, float acc[][4],
                                            int wid, int lane) {
    constexpr int BLO = B_HI_W + 8 * JT * 64;
#pragma unroll
    for (int s = 0; s < 8; s++) {
        uint4 ah4 = *(const uint4*)&smw[A_HI_W + ((wid * 8 + s) * 32 + lane) * 4];
        uint32_t ah[4] = {ah4.x, ah4.y, ah4.z, ah4.w};
        uint32_t al[4];
        if (TERMS >= 2) {
            uint4 al4 = *(const uint4*)&smw[A_LO_W + ((wid * 8 + s) * 32 + lane) * 4];
            al[0] = al4.x; al[1] = al4.y; al[2] = al4.z; al[3] = al4.w;
        }
#pragma unroll
        for (int j = 0; j < JT; j++) {
            uint2 bh2 = *(const uint2*)&smw[B_HI_W + ((s * JT + j) * 32 + lane) * 2];
            uint32_t bh[2] = {bh2.x, bh2.y};
            mma_f16(acc[j], ah, bh);
            if (TERMS >= 2) mma_f16(acc[j], al, bh);
            if (TERMS == 3) {
                uint2 bl2 = *(const uint2*)&smw[BLO + ((s * JT + j) * 32 + lane) * 2];
                uint32_t bl[2] = {bl2.x, bl2.y};
                mma_f16(acc[j], ah, bl);
            }
        }
    }
}

__device__ __forceinline__ void storeZfrag(uint32_t* smw, int lrow, int col,
                                           float v0, float v1) {
    int w = lrow >> 4, r = lrow & 15;
    int s = col >> 4, kk = col & 15;
    int reg = (r >> 3) + 2 * (kk >> 3);
    int lane = (r & 7) * 4 + ((kk & 7) >> 1);
    int idx = ((w * 8 + s) * 32 + lane) * 4 + reg;
    __half h0 = __float2half_rn(v0), h1 = __float2half_rn(v1);
    smw[A_HI_W + idx] = packh2(h0, h1);
    __half l0 = __float2half_rn(v0 - __half2float(h0));
    __half l1 = __float2half_rn(v1 - __half2float(h1));
    smw[A_LO_W + idx] = packh2(l0, l1);
}

// ---------------- fused 4-projection GEMM (layer 1), fp16 HMMA -------------------
__global__ __launch_bounds__(256, 2)
void gemm4_hmma(const float* __restrict__ X,
                const float* __restrict__ W0, const float* __restrict__ b0, float* __restrict__ Q,
                const float* __restrict__ W1, const float* __restrict__ b1,
                const float* __restrict__ W2, const float* __restrict__ b2, __half* __restrict__ KV,
                const float* __restrict__ W3, const float* __restrict__ b3, float* __restrict__ S,
                int n) {
    extern __shared__ uint32_t smw[];
    const int tid = threadIdx.x, wid = tid >> 5, lane = tid & 31;
    const int node0 = blockIdx.x * 128;

    fillA<true>(smw, X, node0, n, tid);

    const float* Wm[4] = {W0, W1, W2, W3};
    const float* bm[4] = {b0, b1, b2, b3};

    int row0 = node0 + wid * 16 + (lane >> 2);
    int row1 = row0 + 8;

    for (int m = 0; m < 4; m++) {
        __syncthreads();
        fillB<128, 0>(smw, Wm[m], tid);
        __syncthreads();

        float acc[16][4];
#pragma unroll
        for (int j = 0; j < 16; j++) {
            float bb0 = __ldg(&bm[m][j * 8 + (lane & 3) * 2]);
            float bb1 = __ldg(&bm[m][j * 8 + (lane & 3) * 2 + 1]);
            acc[j][0] = bb0; acc[j][1] = bb1; acc[j][2] = bb0; acc[j][3] = bb1;
        }
        computeTile<16, 2>(smw, acc, wid, lane);

        if (m == 3) {
            __syncthreads();
            fillB<128, 1>(smw, Wm[m], tid);
            __syncthreads();
            computeTile<16, 1>(smw, acc, wid, lane);
        }

        if (m == 0 || m == 3) {
            float* Y = (m == 0) ? Q : S;
#pragma unroll
            for (int j = 0; j < 16; j++) {
                int col = j * 8 + (lane & 3) * 2;
                if (row0 < n) *(float2*)(Y + (size_t)row0 * 128 + col) = make_float2(acc[j][0], acc[j][1]);
                if (row1 < n) *(float2*)(Y + (size_t)row1 * 128 + col) = make_float2(acc[j][2], acc[j][3]);
            }
        } else {
            int off = (m == 1) ? 0 : 128;
#pragma unroll
            for (int j = 0; j < 16; j++) {
                int col = j * 8 + (lane & 3) * 2;
                if (row0 < n) *(__half2*)(KV + (size_t)row0 * 256 + off + col) = __floats2half2_rn(acc[j][0], acc[j][1]);
                if (row1 < n) *(__half2*)(KV + (size_t)row1 * 256 + off + col) = __floats2half2_rn(acc[j][2], acc[j][3]);
            }
        }
    }
}

// ---------------- fused classifier ------------------------------------------------
__global__ __launch_bounds__(256, 2)
void classifier_hmma(const float* __restrict__ X,
                     const float* __restrict__ Wc1, const float* __restrict__ bc1,
                     const float* __restrict__ Wc2, const float* __restrict__ bc2,
                     const float* __restrict__ Wc3, const float* __restrict__ bc3,
                     float* __restrict__ out, int n) {
    extern __shared__ uint32_t smw[];
    const int tid = threadIdx.x, wid = tid >> 5, lane = tid & 31;
    const int node0 = blockIdx.x * 128;

    fillA<true>(smw, X, node0, n, tid);
    fillB<128, 0>(smw, Wc1, tid);
    __syncthreads();

    float acc[16][4];
#pragma unroll
    for (int j = 0; j < 16; j++) {
        float bb0 = __ldg(&bc1[j * 8 + (lane & 3) * 2]);
        float bb1 = __ldg(&bc1[j * 8 + (lane & 3) * 2 + 1]);
        acc[j][0] = bb0; acc[j][1] = bb1; acc[j][2] = bb0; acc[j][3] = bb1;
    }
    computeTile<16, 2>(smw, acc, wid, lane);
    __syncthreads();
    fillB<128, 1>(smw, Wc1, tid);
    __syncthreads();
    computeTile<16, 1>(smw, acc, wid, lane);
    __syncthreads();

    {
        int lr0 = wid * 16 + (lane >> 2);
        int lr1 = lr0 + 8;
#pragma unroll
        for (int j = 0; j < 16; j++) {
            int col = j * 8 + (lane & 3) * 2;
            storeZfrag(smw, lr0, col, fmaxf(acc[j][0], 0.f), fmaxf(acc[j][1], 0.f));
            storeZfrag(smw, lr1, col, fmaxf(acc[j][2], 0.f), fmaxf(acc[j][3], 0.f));
        }
    }
    __syncthreads();
    fillB<64, 2>(smw, Wc2, tid);
    __syncthreads();

    float acc2[8][4];
#pragma unroll
    for (int j = 0; j < 8; j++) {
        float bb0 = __ldg(&bc2[j * 8 + (lane & 3) * 2]);
        float bb1 = __ldg(&bc2[j * 8 + (lane & 3) * 2 + 1]);
        acc2[j][0] = bb0; acc2[j][1] = bb1; acc2[j][2] = bb0; acc2[j][3] = bb1;
    }
    computeTile<8, 3>(smw, acc2, wid, lane);

    float p0 = 0.f, p1 = 0.f;
#pragma unroll
    for (int j = 0; j < 8; j++) {
        int c = j * 8 + (lane & 3) * 2;
        float w0 = __ldg(&Wc3[c]), w1 = __ldg(&Wc3[c + 1]);
        p0 += fmaxf(acc2[j][0], 0.f) * w0 + fmaxf(acc2[j][1], 0.f) * w1;
        p1 += fmaxf(acc2[j][2], 0.f) * w0 + fmaxf(acc2[j][3], 0.f) * w1;
    }
    p0 += __shfl_xor_sync(0xffffffffu, p0, 1);
    p0 += __shfl_xor_sync(0xffffffffu, p0, 2);
    p1 += __shfl_xor_sync(0xffffffffu, p1, 1);
    p1 += __shfl_xor_sync(0xffffffffu, p1, 2);

    if ((lane & 3) == 0) {
        float bv = __ldg(&bc3[0]);
        int row0 = node0 + wid * 16 + (lane >> 2);
        int row1 = row0 + 8;
        if (row0 < n) out[row0] = p0 + bv;
        if (row1 < n) out[row1] = p1 + bv;
    }
}

// ---------------- edge_index normalization + degree histogram -------------------
__global__ void convert_ei_kernel(const int* __restrict__ p, int E,
                                  int* __restrict__ src, int* __restrict__ dst,
                                  int* __restrict__ deg) {
    __shared__ int s_is64;
    if (threadIdx.x == 0) {
        int is64 = 1;
        for (int i = 0; i < 64; i++)
            if (p[2 * i + 1] != 0) { is64 = 0; break; }
        s_is64 = is64;
    }
    __syncthreads();
    const int is64 = s_is64;
    int e = blockIdx.x * blockDim.x + threadIdx.x;
    if (e >= E) return;
    int s, d;
    if (is64) { s = p[2 * e]; d = p[2 * (E + e)]; }
    else      { s = p[e];     d = p[E + e]; }
    src[e] = s; dst[e] = d;
    atomicAdd(&deg[d], 1);
}

// ---------------- single-block exclusive scan over degrees ----------------------
__global__ void scan_kernel(const int* __restrict__ deg, int* __restrict__ rowptr, int n) {
    __shared__ int sm[1024];
    int tid = threadIdx.x;
    int chunk = (n + 1023) >> 10;
    int start = tid * chunk;
    int end = min(start + chunk, n);
    int sum = 0;
    for (int i = start; i < end; i++) sum += deg[i];
    sm[tid] = sum;
    __syncthreads();
    for (int d = 1; d < 1024; d <<= 1) {
        int v = (tid >= d) ? sm[tid - d] : 0;
        __syncthreads();
        sm[tid] += v;
        __syncthreads();
    }
    int off = sm[tid] - sum;   // exclusive
    for (int i = start; i < end; i++) { rowptr[i] = off; off += deg[i]; }
    if (tid == 1023) rowptr[n] = off;
}

// ---------------- scatter edges into CSR order -----------------------------------
__global__ void scatter_kernel(const int* __restrict__ src, const int* __restrict__ dst,
                               const float* __restrict__ ea,
                               const int* __restrict__ rowptr, int* __restrict__ fill,
                               int* __restrict__ csrc, float* __restrict__ cea, int E) {
    int e = blockIdx.x * blockDim.x + threadIdx.x;
    if (e >= E) return;
    int d = dst[e];
    int pos = rowptr[d] + atomicAdd(&fill[d], 1);
    csrc[pos] = src[e];
    cea[pos]  = ea[e];
}

// ---------------- layer-0 tconv: algebraic collapse (thread per node) ------------
// q.k_src = x0s*A[h] + x1s*B[h] + C[h];  Σex*v = Wv0*sx0 + Wv1*sx1 + bv*den
__global__ __launch_bounds__(256)
void tconv0_kernel(const int* __restrict__ rowptr, const int* __restrict__ csrc,
                   const float* __restrict__ cea, const float* __restrict__ x,
                   const float* __restrict__ Wq, const float* __restrict__ bq,
                   const float* __restrict__ Wk, const float* __restrict__ bk,
                   const float* __restrict__ Wv, const float* __restrict__ bv,
                   const float* __restrict__ Ws, const float* __restrict__ bs,
                   const float* __restrict__ We,
                   float* __restrict__ H, int n) {
    __shared__ float sa[256 * 18];   // per node: sx0[4], sx1[4], den[4], sev[4], x0, x1
    const int tid = threadIdx.x;
    const int node = blockIdx.x * 256 + tid;
    const float SC = 0.17677669529663687f;   // 1/sqrt(32)

    // ---- phase 1: per-node scalar reduction over edges ----
    float A[4], B[4], C[4], QW[4];
    float x0 = 0.f, x1 = 0.f;
    if (node < n) {
        float2 xn = __ldg((const float2*)(x + 2 * (size_t)node));
        x0 = xn.x; x1 = xn.y;
    }
#pragma unroll
    for (int h = 0; h < 4; h++) {
        float a = 0.f, b = 0.f, cc = 0.f, qw = 0.f;
#pragma unroll 8
        for (int j = 0; j < 32; j++) {
            int c = h * 32 + j;
            float qc = fmaf(x0, __ldg(&Wq[c]), fmaf(x1, __ldg(&Wq[HCD + c]), __ldg(&bq[c])));
            a  = fmaf(qc, __ldg(&Wk[c]),       a);
            b  = fmaf(qc, __ldg(&Wk[HCD + c]), b);
            cc = fmaf(qc, __ldg(&bk[c]),       cc);
            qw = fmaf(qc, __ldg(&We[c]),       qw);
        }
        A[h] = a; B[h] = b; C[h] = cc; QW[h] = qw;
    }

    float sx0[4] = {0.f, 0.f, 0.f, 0.f}, sx1[4] = {0.f, 0.f, 0.f, 0.f};
    float den[4] = {0.f, 0.f, 0.f, 0.f}, sev[4] = {0.f, 0.f, 0.f, 0.f};
    int r0 = 0, r1 = 0;
    if (node < n) { r0 = __ldg(&rowptr[node]); r1 = __ldg(&rowptr[node + 1]); }

    int e = r0;
    for (; e + 2 <= r1; e += 2) {
        int   s0 = __ldg(&csrc[e]),  s1 = __ldg(&csrc[e + 1]);
        float a0 = __ldg(&cea[e]),   a1 = __ldg(&cea[e + 1]);
        float2 xa = __ldg((const float2*)(x + 2 * (size_t)s0));
        float2 xb = __ldg((const float2*)(x + 2 * (size_t)s1));
#pragma unroll
        for (int h = 0; h < 4; h++) {
            float p0 = fmaf(xa.x, A[h], fmaf(xa.y, B[h], fmaf(a0, QW[h], C[h])));
            float p1 = fmaf(xb.x, A[h], fmaf(xb.y, B[h], fmaf(a1, QW[h], C[h])));
            float e0 = expf(p0 * SC);
            float e1 = expf(p1 * SC);
            den[h] += e0 + e1;
            sev[h] = fmaf(e0, a0, fmaf(e1, a1, sev[h]));
            sx0[h] = fmaf(e0, xa.x, fmaf(e1, xb.x, sx0[h]));
            sx1[h] = fmaf(e0, xa.y, fmaf(e1, xb.y, sx1[h]));
        }
    }
    if (e < r1) {
        int   s0 = __ldg(&csrc[e]);
        float a0 = __ldg(&cea[e]);
        float2 xa = __ldg((const float2*)(x + 2 * (size_t)s0));
#pragma unroll
        for (int h = 0; h < 4; h++) {
            float p0 = fmaf(xa.x, A[h], fmaf(xa.y, B[h], fmaf(a0, QW[h], C[h])));
            float e0 = expf(p0 * SC);
            den[h] += e0;
            sev[h] = fmaf(e0, a0, sev[h]);
            sx0[h] = fmaf(e0, xa.x, sx0[h]);
            sx1[h] = fmaf(e0, xa.y, sx1[h]);
        }
    }

    float* me = &sa[tid * 18];
#pragma unroll
    for (int h = 0; h < 4; h++) {
        me[h]      = sx0[h];
        me[4 + h]  = sx1[h];
        me[8 + h]  = den[h];
        me[12 + h] = sev[h];
    }
    me[16] = x0; me[17] = x1;
    __syncthreads();

    // ---- phase 2: warp-cooperative coalesced epilogue (warp per node-batch) ----
    const int lane = tid & 31, wid = tid >> 5;
    const int c0 = lane * 4;
    const int h  = lane >> 3;
    float4 wv0 = *(const float4*)(Wv + c0);
    float4 wv1 = *(const float4*)(Wv + HCD + c0);
    float4 bv4 = *(const float4*)(bv + c0);
    float4 we4 = *(const float4*)(We + c0);
    float4 ws0 = *(const float4*)(Ws + c0);
    float4 ws1 = *(const float4*)(Ws + HCD + c0);
    float4 bs4 = *(const float4*)(bs + c0);

    for (int i = 0; i < 32; i++) {
        int nl = wid * 32 + i;
        int gnode = blockIdx.x * 256 + nl;
        if (gnode >= n) break;
        const float* acs = &sa[nl * 18];
        float d  = acs[8 + h];
        float s0 = acs[h];
        float s1 = acs[4 + h];
        float sv = acs[12 + h];
        float xa = acs[16], xb = acs[17];
        float inv = 1.f / (d + 1e-16f);
        float4 o;
        o.x = fmaf(xa, ws0.x, fmaf(xb, ws1.x, bs4.x))
            + (wv0.x * s0 + wv1.x * s1 + bv4.x * d + sv * we4.x) * inv;
        o.y = fmaf(xa, ws0.y, fmaf(xb, ws1.y, bs4.y))
            + (wv0.y * s0 + wv1.y * s1 + bv4.y * d + sv * we4.y) * inv;
        o.z = fmaf(xa, ws0.z, fmaf(xb, ws1.z, bs4.z))
            + (wv0.z * s0 + wv1.z * s1 + bv4.z * d + sv * we4.z) * inv;
        o.w = fmaf(xa, ws0.w, fmaf(xb, ws1.w, bs4.w))
            + (wv0.w * s0 + wv1.w * s1 + bv4.w * d + sv * we4.w) * inv;
        *(float4*)(H + (size_t)gnode * HCD + c0) = o;
    }
}

// ---------------- layer-1 fused edge kernel (fp16 KV gather) ---------------------
__global__ __launch_bounds__(256)
void tconv_kernel(const int* __restrict__ rowptr, const int* __restrict__ csrc,
                  const float* __restrict__ cea,
                  const float* __restrict__ Q, const __half* __restrict__ KV,
                  const float* __restrict__ We,
                  float* __restrict__ H, int n) {
    int node = (blockIdx.x * blockDim.x + threadIdx.x) >> 5;
    if (node >= n) return;
    int lane = threadIdx.x & 31;
    int r0 = __ldg(&rowptr[node]);
    int r1 = __ldg(&rowptr[node + 1]);
    int c0 = lane * 4;

    float4 q = *(const float4*)(Q + (size_t)node * HCD + c0);
    float4 w = *(const float4*)(We + c0);

    float qw = q.x * w.x + q.y * w.y + q.z * w.z + q.w * w.w;
    qw += __shfl_xor_sync(0xffffffffu, qw, 1);
    qw += __shfl_xor_sync(0xffffffffu, qw, 2);
    qw += __shfl_xor_sync(0xffffffffu, qw, 4);

    const float SC = 0.17677669529663687f;
    float den = 0.f, sev = 0.f;
    float4 acc = make_float4(0.f, 0.f, 0.f, 0.f);

    int e = r0;
    for (; e + 4 <= r1; e += 4) {
        int   s0 = __ldg(&csrc[e]),     s1 = __ldg(&csrc[e + 1]);
        int   s2 = __ldg(&csrc[e + 2]), s3 = __ldg(&csrc[e + 3]);
        float a0 = __ldg(&cea[e]),      a1 = __ldg(&cea[e + 1]);
        float a2 = __ldg(&cea[e + 2]),  a3 = __ldg(&cea[e + 3]);

        uint2 k0 = *(const uint2*)(KV + (size_t)s0 * 256 + c0);
        uint2 k1 = *(const uint2*)(KV + (size_t)s1 * 256 + c0);
        uint2 k2 = *(const uint2*)(KV + (size_t)s2 * 256 + c0);
        uint2 k3 = *(const uint2*)(KV + (size_t)s3 * 256 + c0);
        uint2 v0 = *(const uint2*)(KV + (size_t)s0 * 256 + 128 + c0);
        uint2 v1 = *(const uint2*)(KV + (size_t)s1 * 256 + 128 + c0);
        uint2 v2 = *(const uint2*)(KV + (size_t)s2 * 256 + 128 + c0);
        uint2 v3 = *(const uint2*)(KV + (size_t)s3 * 256 + 128 + c0);

        float2 kA, kB;
        kA = __half22float2(*(__half2*)&k0.x); kB = __half22float2(*(__half2*)&k0.y);
        float p0 = q.x * kA.x + q.y * kA.y + q.z * kB.x + q.w * kB.y;
        kA = __half22float2(*(__half2*)&k1.x); kB = __half22float2(*(__half2*)&k1.y);
        float p1 = q.x * kA.x + q.y * kA.y + q.z * kB.x + q.w * kB.y;
        kA = __half22float2(*(__half2*)&k2.x); kB = __half22float2(*(__half2*)&k2.y);
        float p2 = q.x * kA.x + q.y * kA.y + q.z * kB.x + q.w * kB.y;
        kA = __half22float2(*(__half2*)&k3.x); kB = __half22float2(*(__half2*)&k3.y);
        float p3 = q.x * kA.x + q.y * kA.y + q.z * kB.x + q.w * kB.y;

        p0 += __shfl_xor_sync(0xffffffffu, p0, 1);
        p1 += __shfl_xor_sync(0xffffffffu, p1, 1);
        p2 += __shfl_xor_sync(0xffffffffu, p2, 1);
        p3 += __shfl_xor_sync(0xffffffffu, p3, 1);
        p0 += __shfl_xor_sync(0xffffffffu, p0, 2);
        p1 += __shfl_xor_sync(0xffffffffu, p1, 2);
        p2 += __shfl_xor_sync(0xffffffffu, p2, 2);
        p3 += __shfl_xor_sync(0xffffffffu, p3, 2);
        p0 += __shfl_xor_sync(0xffffffffu, p0, 4);
        p1 += __shfl_xor_sync(0xffffffffu, p1, 4);
        p2 += __shfl_xor_sync(0xffffffffu, p2, 4);
        p3 += __shfl_xor_sync(0xffffffffu, p3, 4);

        float ex0 = expf((p0 + a0 * qw) * SC);
        float ex1 = expf((p1 + a1 * qw) * SC);
        float ex2 = expf((p2 + a2 * qw) * SC);
        float ex3 = expf((p3 + a3 * qw) * SC);

        den += (ex0 + ex1) + (ex2 + ex3);
        sev += (ex0 * a0 + ex1 * a1) + (ex2 * a2 + ex3 * a3);

        float2 vA, vB;
        vA = __half22float2(*(__half2*)&v0.x); vB = __half22float2(*(__half2*)&v0.y);
        acc.x = fmaf(vA.x, ex0, acc.x); acc.y = fmaf(vA.y, ex0, acc.y);
        acc.z = fmaf(vB.x, ex0, acc.z); acc.w = fmaf(vB.y, ex0, acc.w);
        vA = __half22float2(*(__half2*)&v1.x); vB = __half22float2(*(__half2*)&v1.y);
        acc.x = fmaf(vA.x, ex1, acc.x); acc.y = fmaf(vA.y, ex1, acc.y);
        acc.z = fmaf(vB.x, ex1, acc.z); acc.w = fmaf(vB.y, ex1, acc.w);
        vA = __half22float2(*(__half2*)&v2.x); vB = __half22float2(*(__half2*)&v2.y);
        acc.x = fmaf(vA.x, ex2, acc.x); acc.y = fmaf(vA.y, ex2, acc.y);
        acc.z = fmaf(vB.x, ex2, acc.z); acc.w = fmaf(vB.y, ex2, acc.w);
        vA = __half22float2(*(__half2*)&v3.x); vB = __half22float2(*(__half2*)&v3.y);
        acc.x = fmaf(vA.x, ex3, acc.x); acc.y = fmaf(vA.y, ex3, acc.y);
        acc.z = fmaf(vB.x, ex3, acc.z); acc.w = fmaf(vB.y, ex3, acc.w);
    }
    for (; e < r1; e++) {
        int   s0 = __ldg(&csrc[e]);
        float a0 = __ldg(&cea[e]);
        uint2 k0 = *(const uint2*)(KV + (size_t)s0 * 256 + c0);
        uint2 v0 = *(const uint2*)(KV + (size_t)s0 * 256 + 128 + c0);
        float2 kA = __half22float2(*(__half2*)&k0.x);
        float2 kB = __half22float2(*(__half2*)&k0.y);
        float p0 = q.x * kA.x + q.y * kA.y + q.z * kB.x + q.w * kB.y;
        p0 += __shfl_xor_sync(0xffffffffu, p0, 1);
        p0 += __shfl_xor_sync(0xffffffffu, p0, 2);
        p0 += __shfl_xor_sync(0xffffffffu, p0, 4);
        float ex0 = expf((p0 + a0 * qw) * SC);
        den += ex0;
        sev += ex0 * a0;
        float2 vA = __half22float2(*(__half2*)&v0.x);
        float2 vB = __half22float2(*(__half2*)&v0.y);
        acc.x = fmaf(vA.x, ex0, acc.x); acc.y = fmaf(vA.y, ex0, acc.y);
        acc.z = fmaf(vB.x, ex0, acc.z); acc.w = fmaf(vB.y, ex0, acc.w);
    }

    float inv = 1.f / (den + 1e-16f);
    float4 out = *(const float4*)(H + (size_t)node * HCD + c0);  // skip term
    out.x = fmaf(fmaf(sev, w.x, acc.x), inv, out.x);
    out.y = fmaf(fmaf(sev, w.y, acc.y), inv, out.y);
    out.z = fmaf(fmaf(sev, w.z, acc.z), inv, out.z);
    out.w = fmaf(fmaf(sev, w.w, acc.w), inv, out.w);
    *(float4*)(H + (size_t)node * HCD + c0) = out;
}

// ---------------- launch -----------------------------------------------------------
extern "C" void kernel_launch(void* const* d_in, const int* in_sizes, int n_in,
                              void* d_out, int out_size) {
    const float* x   = (const float*)d_in[0];
    const int*   eiw = (const int*)d_in[1];
    const float* ea  = (const float*)d_in[2];
    const float *Wq0 = (const float*)d_in[3],  *bq0 = (const float*)d_in[4];
    const float *Wk0 = (const float*)d_in[5],  *bk0 = (const float*)d_in[6];
    const float *Wv0 = (const float*)d_in[7],  *bv0 = (const float*)d_in[8];
    const float *We0 = (const float*)d_in[9];
    const float *Ws0 = (const float*)d_in[10], *bs0 = (const float*)d_in[11];
    const float *Wq1 = (const float*)d_in[12], *bq1 = (const float*)d_in[13];
    const float *Wk1 = (const float*)d_in[14], *bk1 = (const float*)d_in[15];
    const float *Wv1 = (const float*)d_in[16], *bv1 = (const float*)d_in[17];
    const float *We1 = (const float*)d_in[18];
    const float *Ws1 = (const float*)d_in[19], *bs1 = (const float*)d_in[20];
    const float *Wc1 = (const float*)d_in[21], *bc1 = (const float*)d_in[22];
    const float *Wc2 = (const float*)d_in[23], *bc2 = (const float*)d_in[24];
    const float *Wc3 = (const float*)d_in[25], *bc3 = (const float*)d_in[26];

    const int n = in_sizes[0] / 2;
    const int E = in_sizes[2];

    float *Q, *Ha, *Hb, *cea;
    __half* KV;
    int *src, *dst, *deg, *rowptr, *fill, *csrc;
    cudaGetSymbolAddress((void**)&Q,      g_Q);
    cudaGetSymbolAddress((void**)&KV,     g_KV);
    cudaGetSymbolAddress((void**)&Ha,     g_Ha);
    cudaGetSymbolAddress((void**)&Hb,     g_Hb);
    cudaGetSymbolAddress((void**)&src,    g_src);
    cudaGetSymbolAddress((void**)&dst,    g_dst);
    cudaGetSymbolAddress((void**)&deg,    g_deg);
    cudaGetSymbolAddress((void**)&rowptr, g_rowptr);
    cudaGetSymbolAddress((void**)&fill,   g_fill);
    cudaGetSymbolAddress((void**)&csrc,   g_csrc);
    cudaGetSymbolAddress((void**)&cea,    g_cea);

    const int TB = 256;
    const int EB = (E + TB - 1) / TB;
    dim3 nodeWarpGrid((n * 32 + TB - 1) / TB);
    dim3 nodeThreadGrid((n + TB - 1) / TB);
    dim3 tileGrid((n + 127) / 128);

    const int SMEM = 24576 * 4;   // 96 KB
    cudaFuncSetAttribute(gemm4_hmma,      cudaFuncAttributeMaxDynamicSharedMemorySize, SMEM);
    cudaFuncSetAttribute(classifier_hmma, cudaFuncAttributeMaxDynamicSharedMemorySize, SMEM);

    cudaMemsetAsync(deg,  0, (n + 1) * sizeof(int));
    cudaMemsetAsync(fill, 0, n * sizeof(int));
    convert_ei_kernel<<<EB, TB>>>(eiw, E, src, dst, deg);                          // k1
    scan_kernel<<<1, 1024>>>(deg, rowptr, n);                                       // k2
    scatter_kernel<<<EB, TB>>>(src, dst, ea, rowptr, fill, csrc, cea, E);           // k3
    tconv0_kernel<<<nodeThreadGrid, TB>>>(rowptr, csrc, cea, x,                     // k4 <- profiled
                                          Wq0, bq0, Wk0, bk0, Wv0, bv0, Ws0, bs0,
                                          We0, Ha, n);
    gemm4_hmma<<<tileGrid, 256, SMEM>>>(Ha,                                         // k5
                                        Wq1, bq1, Q,
                                        Wk1, bk1,
                                        Wv1, bv1, KV,
                                        Ws1, bs1, Hb, n);
    tconv_kernel<<<nodeWarpGrid, TB>>>(rowptr, csrc, cea, Q, KV, We1, Hb, n);      // k6
    classifier_hmma<<<tileGrid, 256, SMEM>>>(Hb, Wc1, bc1, Wc2, bc2, Wc3, bc3,      // k7
                                             (float*)d_out, n);
}